// round 1
// baseline (speedup 1.0000x reference)
#include <cuda_runtime.h>
#include <math.h>

#define Bb   8
#define Ss   1024
#define Dd   768
#define FFf  3072
#define Ee   8
#define KK   2

// ---------------- scratch (no allocations allowed) ----------------
__device__ float g_h[(size_t)Bb * KK * Ss * FFf];      // [B,K,S,FF] post-GELU, 201MB
__device__ float g_mixed[(size_t)Bb * Ss * Dd];        // [B,S,D]
__device__ int   g_topi[Bb * KK];
__device__ float g_topv[Bb * KK];

// ---------------- kernel 1: router ----------------
__global__ void router_kernel(const float* __restrict__ x,
                              const float* __restrict__ ts,
                              const float* __restrict__ rw,
                              const float* __restrict__ rb,
                              float* __restrict__ probs_out) {
    int b   = blockIdx.x;
    int tid = threadIdx.x;
    __shared__ float feat[2 * Dd];
    // mean pool over S, coalesced over d
    for (int d = tid; d < Dd; d += 256) {
        float acc = 0.f;
        const float* xb = x + (size_t)b * Ss * Dd + d;
        for (int s = 0; s < Ss; s++) acc += xb[(size_t)s * Dd];
        feat[d]      = acc * (1.0f / Ss);
        feat[Dd + d] = ts[b * Dd + d];
    }
    __syncthreads();

    __shared__ float red[256];
    __shared__ float logits[Ee];
    for (int e = 0; e < Ee; e++) {
        float p = 0.f;
        for (int d = tid; d < 2 * Dd; d += 256) p += feat[d] * rw[d * Ee + e];
        red[tid] = p;
        __syncthreads();
        for (int s = 128; s > 0; s >>= 1) {
            if (tid < s) red[tid] += red[tid + s];
            __syncthreads();
        }
        if (tid == 0) logits[e] = red[0] + rb[e];
        __syncthreads();
    }

    if (tid == 0) {
        float mx = logits[0];
        for (int e = 1; e < Ee; e++) mx = fmaxf(mx, logits[e]);
        float p[Ee], den = 0.f;
        for (int e = 0; e < Ee; e++) { p[e] = expf(logits[e] - mx); den += p[e]; }
        float inv = 1.f / den;
        for (int e = 0; e < Ee; e++) { p[e] *= inv; probs_out[b * Ee + e] = p[e]; }
        // top-2 (first occurrence wins ties, matching lax.top_k)
        int i0 = 0;
        for (int e = 1; e < Ee; e++) if (p[e] > p[i0]) i0 = e;
        int i1 = -1;
        for (int e = 0; e < Ee; e++) {
            if (e == i0) continue;
            if (i1 < 0 || p[e] > p[i1]) i1 = e;
        }
        g_topi[b * KK + 0] = i0;  g_topv[b * KK + 0] = p[i0];
        g_topi[b * KK + 1] = i1;  g_topv[b * KK + 1] = p[i1];
    }
}

// ---------------- GEMM tiling constants ----------------
#define TM  64
#define TN  64
#define TKC 16

__device__ __forceinline__ float gelu_tanh(float v) {
    float v3 = v * v * v;
    float t  = tanhf(0.7978845608028654f * (v + 0.044715f * v3));
    return 0.5f * v * (1.f + t);
}

// ---------------- kernel 2: h = gelu(x @ W1[e] + b1[e]) ----------------
__global__ void gemm1_kernel(const float* __restrict__ x,
                             const float* __restrict__ W1,
                             const float* __restrict__ b1) {
    int bk = blockIdx.z;             // b*KK + k
    int b  = bk / KK;
    int e  = g_topi[bk];
    int s0 = blockIdx.y * TM;
    int f0 = blockIdx.x * TN;

    const float* A  = x  + (size_t)b * Ss * Dd;       // [S, D]
    const float* Bw = W1 + (size_t)e * Dd * FFf;      // [D, FF]

    __shared__ float As[TKC][TM];
    __shared__ float Bs[TKC][TN];

    int tid = threadIdx.x;
    int tx = tid & 15, ty = tid >> 4;
    float acc[4][4] = {};

    for (int kk = 0; kk < Dd; kk += TKC) {
        {   // A tile: 64 rows x 16 k; each thread one float4 along k
            int row = tid >> 2;
            int kq  = (tid & 3) * 4;
            float4 v = *(const float4*)(A + (size_t)(s0 + row) * Dd + kk + kq);
            As[kq + 0][row] = v.x; As[kq + 1][row] = v.y;
            As[kq + 2][row] = v.z; As[kq + 3][row] = v.w;
        }
        {   // B tile: 16 rows x 64 f; float4 along f
            int row = tid >> 4;
            int cq  = (tid & 15) * 4;
            *(float4*)&Bs[row][cq] =
                *(const float4*)(Bw + (size_t)(kk + row) * FFf + f0 + cq);
        }
        __syncthreads();
#pragma unroll
        for (int kq = 0; kq < TKC; kq++) {
            float a[4], bb[4];
#pragma unroll
            for (int i = 0; i < 4; i++) a[i]  = As[kq][ty * 4 + i];
#pragma unroll
            for (int j = 0; j < 4; j++) bb[j] = Bs[kq][tx * 4 + j];
#pragma unroll
            for (int i = 0; i < 4; i++)
#pragma unroll
                for (int j = 0; j < 4; j++) acc[i][j] = fmaf(a[i], bb[j], acc[i][j]);
        }
        __syncthreads();
    }

    float* H = g_h + (size_t)bk * Ss * FFf;
#pragma unroll
    for (int i = 0; i < 4; i++) {
        int s = s0 + ty * 4 + i;
#pragma unroll
        for (int j = 0; j < 4; j++) {
            int f = f0 + tx * 4 + j;
            float v = acc[i][j] + b1[e * FFf + f];
            H[(size_t)s * FFf + f] = gelu_tanh(v);
        }
    }
}

// ---------------- kernel 3: mixed = sum_k topv * (h @ W2[e] + b2[e]) ----------------
__global__ void gemm2_kernel(const float* __restrict__ W2,
                             const float* __restrict__ b2) {
    int b  = blockIdx.z;
    int s0 = blockIdx.y * TM;
    int d0 = blockIdx.x * TN;

    __shared__ float As[TKC][TM];
    __shared__ float Bs[TKC][TN];

    int tid = threadIdx.x;
    int tx = tid & 15, ty = tid >> 4;
    float out[4][4] = {};

    for (int k = 0; k < KK; k++) {
        int   e = g_topi[b * KK + k];
        float w = g_topv[b * KK + k];
        const float* A  = g_h + (size_t)(b * KK + k) * Ss * FFf;  // [S, FF]
        const float* Bw = W2  + (size_t)e * FFf * Dd;             // [FF, D]

        float acc[4][4] = {};
        for (int kk = 0; kk < FFf; kk += TKC) {
            {
                int row = tid >> 2;
                int kq  = (tid & 3) * 4;
                float4 v = *(const float4*)(A + (size_t)(s0 + row) * FFf + kk + kq);
                As[kq + 0][row] = v.x; As[kq + 1][row] = v.y;
                As[kq + 2][row] = v.z; As[kq + 3][row] = v.w;
            }
            {
                int row = tid >> 4;
                int cq  = (tid & 15) * 4;
                *(float4*)&Bs[row][cq] =
                    *(const float4*)(Bw + (size_t)(kk + row) * Dd + d0 + cq);
            }
            __syncthreads();
#pragma unroll
            for (int kq = 0; kq < TKC; kq++) {
                float a[4], bb[4];
#pragma unroll
                for (int i = 0; i < 4; i++) a[i]  = As[kq][ty * 4 + i];
#pragma unroll
                for (int j = 0; j < 4; j++) bb[j] = Bs[kq][tx * 4 + j];
#pragma unroll
                for (int i = 0; i < 4; i++)
#pragma unroll
                    for (int j = 0; j < 4; j++) acc[i][j] = fmaf(a[i], bb[j], acc[i][j]);
            }
            __syncthreads();
        }
#pragma unroll
        for (int i = 0; i < 4; i++)
#pragma unroll
            for (int j = 0; j < 4; j++)
                out[i][j] += w * (acc[i][j] + b2[e * Dd + d0 + tx * 4 + j]);
    }

    float* M = g_mixed + (size_t)b * Ss * Dd;
#pragma unroll
    for (int i = 0; i < 4; i++) {
        int s = s0 + ty * 4 + i;
#pragma unroll
        for (int j = 0; j < 4; j++)
            M[(size_t)s * Dd + d0 + tx * 4 + j] = out[i][j];
    }
}

// ---------------- kernel 4: out = x + LN(mixed) ----------------
__global__ void ln_kernel(const float* __restrict__ x,
                          const float* __restrict__ gamma,
                          const float* __restrict__ beta,
                          float* __restrict__ out) {
    int row = blockIdx.x;            // b*S + s
    int tid = threadIdx.x;           // 256, D = 3*256
    const float* m = g_mixed + (size_t)row * Dd;

    float v0 = m[tid], v1 = m[tid + 256], v2 = m[tid + 512];
    __shared__ float red[256], red2[256];
    red[tid]  = v0 + v1 + v2;
    red2[tid] = v0 * v0 + v1 * v1 + v2 * v2;
    __syncthreads();
    for (int s = 128; s > 0; s >>= 1) {
        if (tid < s) { red[tid] += red[tid + s]; red2[tid] += red2[tid + s]; }
        __syncthreads();
    }
    __shared__ float smu, sinv;
    if (tid == 0) {
        float mu  = red[0] * (1.0f / Dd);
        float var = red2[0] * (1.0f / Dd) - mu * mu;
        smu = mu; sinv = rsqrtf(var + 1e-5f);
    }
    __syncthreads();
    float mu = smu, inv = sinv;
    const float* xr = x + (size_t)row * Dd;
    float* o = out + (size_t)row * Dd;
#pragma unroll
    for (int q = 0; q < 3; q++) {
        int d = tid + q * 256;
        float mv = m[d];
        o[d] = xr[d] + (mv - mu) * inv * gamma[d] + beta[d];
    }
}

// ---------------- launch ----------------
extern "C" void kernel_launch(void* const* d_in, const int* in_sizes, int n_in,
                              void* d_out, int out_size) {
    const float* x   = (const float*)d_in[0];
    const float* ts  = (const float*)d_in[1];
    const float* W1  = (const float*)d_in[2];
    const float* b1  = (const float*)d_in[3];
    const float* W2  = (const float*)d_in[4];
    const float* b2  = (const float*)d_in[5];
    const float* rw  = (const float*)d_in[6];
    const float* rb  = (const float*)d_in[7];
    const float* gam = (const float*)d_in[8];
    const float* bet = (const float*)d_in[9];

    float* out   = (float*)d_out;
    float* probs = out + (size_t)Bb * Ss * Dd;   // tuple output: (out, probs) concatenated

    router_kernel<<<Bb, 256>>>(x, ts, rw, rb, probs);

    dim3 g1(FFf / TN, Ss / TM, Bb * KK);
    gemm1_kernel<<<g1, 256>>>(x, W1, b1);

    dim3 g2(Dd / TN, Ss / TM, Bb);
    gemm2_kernel<<<g2, 256>>>(W2, b2);

    ln_kernel<<<Bb * Ss, 256>>>(x, gam, bet, out);
}

// round 4
// speedup vs baseline: 2.4882x; 2.4882x over previous
#include <cuda_runtime.h>
#include <cuda_bf16.h>
#include <math.h>
#include <stdint.h>

#define Bb 8
#define Ss 1024
#define Dd 768
#define FFf 3072
#define Ee 8
#define KK 2

// ======================= scratch (no allocs allowed) =======================
__device__ __nv_bfloat16 g_xh[(size_t)Bb * Ss * Dd];
__device__ __nv_bfloat16 g_xl[(size_t)Bb * Ss * Dd];
__device__ __nv_bfloat16 g_w1h[(size_t)Ee * FFf * Dd];   // W1^T [E,FF,D]
__device__ __nv_bfloat16 g_w1l[(size_t)Ee * FFf * Dd];
__device__ __nv_bfloat16 g_w2h[(size_t)Ee * Dd * FFf];   // W2^T [E,D,FF]
__device__ __nv_bfloat16 g_w2l[(size_t)Ee * Dd * FFf];
__device__ __nv_bfloat16 g_hh[(size_t)Bb * KK * Ss * FFf]; // topv*gelu(xW1+b1) hi
__device__ __nv_bfloat16 g_hl[(size_t)Bb * KK * Ss * FFf]; // lo
__device__ float g_mixed[(size_t)Bb * Ss * Dd];
__device__ int   g_topi[Bb * KK];
__device__ float g_topv[Bb * KK];

// ======================= PTX helpers (base ISA only: sm_80 era) =======================
__device__ __forceinline__ uint32_t smem_u32(const void* p) {
    uint32_t a;
    asm("{ .reg .u64 t; cvta.to.shared.u64 t, %1; cvt.u32.u64 %0, t; }"
        : "=r"(a) : "l"(p));
    return a;
}
__device__ __forceinline__ void cp16(uint32_t s, const void* g) {
    asm volatile("cp.async.cg.shared.global [%0], [%1], 16;" :: "r"(s), "l"(g) : "memory");
}
#define CP_COMMIT() asm volatile("cp.async.commit_group;" ::: "memory")
#define CP_WAIT1()  asm volatile("cp.async.wait_group 1;" ::: "memory")
#define CP_WAIT0()  asm volatile("cp.async.wait_group 0;" ::: "memory")

#define LDSM4(r, addr) \
    asm volatile("ldmatrix.sync.aligned.m8n8.x4.shared.b16 {%0,%1,%2,%3}, [%4];" \
        : "=r"((r)[0]), "=r"((r)[1]), "=r"((r)[2]), "=r"((r)[3]) : "r"(addr))

__device__ __forceinline__ void mma16816(float* d, const uint32_t* a, const uint32_t* b) {
    asm volatile(
        "mma.sync.aligned.m16n8k16.row.col.f32.bf16.bf16.f32 "
        "{%0,%1,%2,%3}, {%4,%5,%6,%7}, {%8,%9}, {%0,%1,%2,%3};"
        : "+f"(d[0]), "+f"(d[1]), "+f"(d[2]), "+f"(d[3])
        : "r"(a[0]), "r"(a[1]), "r"(a[2]), "r"(a[3]), "r"(b[0]), "r"(b[1]));
}

__device__ __forceinline__ float gelu_tanh(float v) {
    float v3 = v * v * v;
    float t  = tanhf(0.7978845608028654f * (v + 0.044715f * v3));
    return 0.5f * v * (1.f + t);
}

// smem tile geometry: 128 rows x 32 bf16, rows padded to 40 bf16 (80B)
#define ROWB  80
#define ARRB  10240                 // 128 * 80
#define STAGE 40960                 // 4 arrays (Ah, Al, Bh, Bl)
#define SMEM_BYTES (2 * STAGE)

// load one stage: A tile (128 x 32) hi/lo + B tile (128 x 32) hi/lo
__device__ __forceinline__ void load_stage(uint32_t sbase,
                                           const __nv_bfloat16* Ah, const __nv_bfloat16* Al, size_t ldA,
                                           const __nv_bfloat16* Bh, const __nv_bfloat16* Bl, size_t ldB,
                                           int tid) {
#pragma unroll
    for (int i = 0; i < 2; i++) {
        int c   = tid + i * 256;
        int row = c >> 2, q = c & 3;
        uint32_t so = (uint32_t)(row * ROWB + q * 16);
        size_t goA = (size_t)row * ldA + q * 8;
        size_t goB = (size_t)row * ldB + q * 8;
        cp16(sbase + so,            Ah + goA);
        cp16(sbase + ARRB + so,     Al + goA);
        cp16(sbase + 2 * ARRB + so, Bh + goB);
        cp16(sbase + 3 * ARRB + so, Bl + goB);
    }
}

// compute one K=32 stage: D += Ah*Bh + Ah*Bl + Al*Bh   (warp tile 32M x 64N)
__device__ __forceinline__ void compute_stage(uint32_t sbase, int wm, int wn, int lane,
                                              float d[2][8][4]) {
#pragma unroll
    for (int kb = 0; kb < 2; kb++) {
        uint32_t ah[2][4], al[2][4];
#pragma unroll
        for (int mt = 0; mt < 2; mt++) {
            int row  = wm * 32 + mt * 16 + (lane & 15);
            int kcol = kb * 16 + (lane >> 4) * 8;
            uint32_t ad = sbase + row * ROWB + kcol * 2;
            LDSM4(ah[mt], ad);
            LDSM4(al[mt], ad + ARRB);
        }
        uint32_t bh[8][2], bl[8][2];
#pragma unroll
        for (int p = 0; p < 4; p++) {
            int n    = wn * 64 + p * 16 + ((lane >> 4) & 1) * 8 + (lane & 7);
            int kcol = kb * 16 + ((lane >> 3) & 1) * 8;
            uint32_t bd = sbase + 2 * ARRB + n * ROWB + kcol * 2;
            uint32_t r[4];
            LDSM4(r, bd);
            bh[2 * p][0] = r[0]; bh[2 * p][1] = r[1];
            bh[2 * p + 1][0] = r[2]; bh[2 * p + 1][1] = r[3];
            LDSM4(r, bd + ARRB);
            bl[2 * p][0] = r[0]; bl[2 * p][1] = r[1];
            bl[2 * p + 1][0] = r[2]; bl[2 * p + 1][1] = r[3];
        }
#pragma unroll
        for (int mt = 0; mt < 2; mt++)
#pragma unroll
            for (int nt = 0; nt < 8; nt++) {
                mma16816(d[mt][nt], ah[mt], bh[nt]);
                mma16816(d[mt][nt], ah[mt], bl[nt]);
                mma16816(d[mt][nt], al[mt], bh[nt]);
            }
    }
}

// ======================= kernel: router =======================
__global__ void router_kernel(const float* __restrict__ x,
                              const float* __restrict__ ts,
                              const float* __restrict__ rw,
                              const float* __restrict__ rb,
                              float* __restrict__ probs_out) {
    int b   = blockIdx.x;
    int tid = threadIdx.x;
    __shared__ float feat[2 * Dd];
    for (int d = tid; d < Dd; d += 256) {
        float acc = 0.f;
        const float* xb = x + (size_t)b * Ss * Dd + d;
        for (int s = 0; s < Ss; s++) acc += xb[(size_t)s * Dd];
        feat[d]      = acc * (1.0f / Ss);
        feat[Dd + d] = ts[b * Dd + d];
    }
    __syncthreads();

    __shared__ float red[256];
    __shared__ float logits[Ee];
    for (int e = 0; e < Ee; e++) {
        float p = 0.f;
        for (int d = tid; d < 2 * Dd; d += 256) p += feat[d] * rw[d * Ee + e];
        red[tid] = p;
        __syncthreads();
        for (int s = 128; s > 0; s >>= 1) {
            if (tid < s) red[tid] += red[tid + s];
            __syncthreads();
        }
        if (tid == 0) logits[e] = red[0] + rb[e];
        __syncthreads();
    }

    if (tid == 0) {
        float mx = logits[0];
        for (int e = 1; e < Ee; e++) mx = fmaxf(mx, logits[e]);
        float p[Ee], den = 0.f;
        for (int e = 0; e < Ee; e++) { p[e] = expf(logits[e] - mx); den += p[e]; }
        float inv = 1.f / den;
        for (int e = 0; e < Ee; e++) { p[e] *= inv; probs_out[b * Ee + e] = p[e]; }
        int i0 = 0;
        for (int e = 1; e < Ee; e++) if (p[e] > p[i0]) i0 = e;
        int i1 = -1;
        for (int e = 0; e < Ee; e++) {
            if (e == i0) continue;
            if (i1 < 0 || p[e] > p[i1]) i1 = e;
        }
        g_topi[b * KK + 0] = i0;  g_topv[b * KK + 0] = p[i0];
        g_topi[b * KK + 1] = i1;  g_topv[b * KK + 1] = p[i1];
    }
}

// ======================= kernel: split x into bf16 hi/lo =======================
__global__ void split_x_kernel(const float* __restrict__ x) {
    size_t i = ((size_t)blockIdx.x * blockDim.x + threadIdx.x) * 4;
    float4 v = *(const float4*)(x + i);
    float vv[4] = {v.x, v.y, v.z, v.w};
    __nv_bfloat16 h[4], l[4];
#pragma unroll
    for (int j = 0; j < 4; j++) {
        h[j] = __float2bfloat16_rn(vv[j]);
        l[j] = __float2bfloat16_rn(vv[j] - __bfloat162float(h[j]));
    }
    __nv_bfloat162 h01 = __halves2bfloat162(h[0], h[1]);
    __nv_bfloat162 h23 = __halves2bfloat162(h[2], h[3]);
    __nv_bfloat162 l01 = __halves2bfloat162(l[0], l[1]);
    __nv_bfloat162 l23 = __halves2bfloat162(l[2], l[3]);
    uint2 uh, ul;
    uh.x = *(uint32_t*)&h01; uh.y = *(uint32_t*)&h23;
    ul.x = *(uint32_t*)&l01; ul.y = *(uint32_t*)&l23;
    *(uint2*)(g_xh + i) = uh;
    *(uint2*)(g_xl + i) = ul;
}

// ======================= kernel: transpose + split W =======================
// in: W [E, R, C]  ->  out [E, C, R] bf16 hi/lo.  which=0 -> W1, which=1 -> W2
__global__ void split_w_kernel(const float* __restrict__ W, int which, int R, int C) {
    __shared__ float t[32][33];
    int e  = blockIdx.z;
    int c0 = blockIdx.x * 32, r0 = blockIdx.y * 32;
    const float* Wp = W + (size_t)e * R * C;
#pragma unroll
    for (int i = 0; i < 4; i++) {
        int r = r0 + threadIdx.y + i * 8;
        t[threadIdx.y + i * 8][threadIdx.x] = Wp[(size_t)r * C + c0 + threadIdx.x];
    }
    __syncthreads();
    __nv_bfloat16* th = which ? g_w2h : g_w1h;
    __nv_bfloat16* tl = which ? g_w2l : g_w1l;
#pragma unroll
    for (int i = 0; i < 4; i++) {
        int c = c0 + threadIdx.y + i * 8;
        float v = t[threadIdx.x][threadIdx.y + i * 8];
        __nv_bfloat16 h = __float2bfloat16_rn(v);
        __nv_bfloat16 l = __float2bfloat16_rn(v - __bfloat162float(h));
        size_t o = ((size_t)e * C + c) * R + r0 + threadIdx.x;
        th[o] = h; tl[o] = l;
    }
}

// ======================= GEMM1: h = topv * gelu(x W1 + b1)  (mma.sync) =======================
// grid (FFf/128, Ss/128, B*K), 256 threads, tile 128x128, K=768
__global__ __launch_bounds__(256, 1) void gemm1_mma(const float* __restrict__ b1) {
    extern __shared__ char smraw[];
    uint32_t sb = smem_u32(smraw);

    int tid = threadIdx.x, lane = tid & 31, warp = tid >> 5;
    int wm = warp & 3, wn = warp >> 2;
    int bk = blockIdx.z;
    int b  = bk >> 1;
    int e  = g_topi[bk];
    int s0 = blockIdx.y * 128, f0 = blockIdx.x * 128;

    const __nv_bfloat16* Ah = g_xh  + ((size_t)b * Ss + s0) * Dd;
    const __nv_bfloat16* Al = g_xl  + ((size_t)b * Ss + s0) * Dd;
    const __nv_bfloat16* Bh = g_w1h + ((size_t)e * FFf + f0) * Dd;
    const __nv_bfloat16* Bl = g_w1l + ((size_t)e * FFf + f0) * Dd;

    float d[2][8][4];
#pragma unroll
    for (int mt = 0; mt < 2; mt++)
#pragma unroll
        for (int nt = 0; nt < 8; nt++)
#pragma unroll
            for (int q = 0; q < 4; q++) d[mt][nt][q] = 0.f;

    const int nk = Dd / 32;    // 24
    load_stage(sb, Ah, Al, Dd, Bh, Bl, Dd, tid);
    CP_COMMIT();

    for (int ks = 0; ks < nk; ks++) {
        uint32_t buf = (ks & 1) ? sb + STAGE : sb;
        if (ks + 1 < nk) {
            int kk = (ks + 1) * 32;
            uint32_t nbuf = ((ks + 1) & 1) ? sb + STAGE : sb;
            load_stage(nbuf, Ah + kk, Al + kk, Dd, Bh + kk, Bl + kk, Dd, tid);
            CP_COMMIT();
            CP_WAIT1();
        } else {
            CP_WAIT0();
        }
        __syncthreads();
        compute_stage(buf, wm, wn, lane, d);
        __syncthreads();
    }

    // epilogue: + b1, gelu, * topv, split to bf16 hi/lo
    const float* b1e = b1 + (size_t)e * FFf + f0;
    float w = g_topv[bk];
    int lrow = lane >> 2;
    int lcol = (lane & 3) * 2;
#pragma unroll
    for (int mt = 0; mt < 2; mt++) {
#pragma unroll
        for (int nt = 0; nt < 8; nt++) {
            int f  = f0 + wn * 64 + nt * 8 + lcol;
            float bb0 = b1e[wn * 64 + nt * 8 + lcol];
            float bb1 = b1e[wn * 64 + nt * 8 + lcol + 1];
#pragma unroll
            for (int half = 0; half < 2; half++) {
                int s = s0 + wm * 32 + mt * 16 + lrow + half * 8;
                float g0 = w * gelu_tanh(d[mt][nt][2 * half]     + bb0);
                float g1 = w * gelu_tanh(d[mt][nt][2 * half + 1] + bb1);
                __nv_bfloat16 h0 = __float2bfloat16_rn(g0);
                __nv_bfloat16 h1 = __float2bfloat16_rn(g1);
                __nv_bfloat16 l0 = __float2bfloat16_rn(g0 - __bfloat162float(h0));
                __nv_bfloat16 l1 = __float2bfloat16_rn(g1 - __bfloat162float(h1));
                __nv_bfloat162 hh = __halves2bfloat162(h0, h1);
                __nv_bfloat162 ll = __halves2bfloat162(l0, l1);
                size_t off = ((size_t)bk * Ss + s) * FFf + f;
                *(uint32_t*)(g_hh + off) = *(uint32_t*)&hh;
                *(uint32_t*)(g_hl + off) = *(uint32_t*)&ll;
            }
        }
    }
}

// ======================= GEMM2: mixed = sum_k (h_k W2[e_k] + topv_k b2[e_k]) =======================
// grid (Dd/128, Ss/128, B), 256 threads, tile 128x128, K = 2 * 3072
__global__ __launch_bounds__(256, 1) void gemm2_mma(const float* __restrict__ b2) {
    extern __shared__ char smraw[];
    uint32_t sb = smem_u32(smraw);

    int tid = threadIdx.x, lane = tid & 31, warp = tid >> 5;
    int wm = warp & 3, wn = warp >> 2;
    int b  = blockIdx.z;
    int s0 = blockIdx.y * 128, d0 = blockIdx.x * 128;
    int e0 = g_topi[b * 2], e1 = g_topi[b * 2 + 1];

    float d[2][8][4];
#pragma unroll
    for (int mt = 0; mt < 2; mt++)
#pragma unroll
        for (int nt = 0; nt < 8; nt++)
#pragma unroll
            for (int q = 0; q < 4; q++) d[mt][nt][q] = 0.f;

    const int nk = 2 * FFf / 32;   // 192

    // stage-kt pointer helpers
    const __nv_bfloat16* Ah0 = g_hh + ((size_t)(b * 2 + 0) * Ss + s0) * FFf;
    const __nv_bfloat16* Al0 = g_hl + ((size_t)(b * 2 + 0) * Ss + s0) * FFf;
    const __nv_bfloat16* Ah1 = g_hh + ((size_t)(b * 2 + 1) * Ss + s0) * FFf;
    const __nv_bfloat16* Al1 = g_hl + ((size_t)(b * 2 + 1) * Ss + s0) * FFf;
    const __nv_bfloat16* Bh0 = g_w2h + ((size_t)e0 * Dd + d0) * FFf;
    const __nv_bfloat16* Bl0 = g_w2l + ((size_t)e0 * Dd + d0) * FFf;
    const __nv_bfloat16* Bh1 = g_w2h + ((size_t)e1 * Dd + d0) * FFf;
    const __nv_bfloat16* Bl1 = g_w2l + ((size_t)e1 * Dd + d0) * FFf;

    load_stage(sb, Ah0, Al0, FFf, Bh0, Bl0, FFf, tid);
    CP_COMMIT();

    for (int ks = 0; ks < nk; ks++) {
        uint32_t buf = (ks & 1) ? sb + STAGE : sb;
        if (ks + 1 < nk) {
            int kt = ks + 1;
            int k2 = kt / 96;
            int kk = (kt - k2 * 96) * 32;
            uint32_t nbuf = (kt & 1) ? sb + STAGE : sb;
            if (k2 == 0)
                load_stage(nbuf, Ah0 + kk, Al0 + kk, FFf, Bh0 + kk, Bl0 + kk, FFf, tid);
            else
                load_stage(nbuf, Ah1 + kk, Al1 + kk, FFf, Bh1 + kk, Bl1 + kk, FFf, tid);
            CP_COMMIT();
            CP_WAIT1();
        } else {
            CP_WAIT0();
        }
        __syncthreads();
        compute_stage(buf, wm, wn, lane, d);
        __syncthreads();
    }

    // epilogue: + topv-weighted biases, fp32 out
    float tv0 = g_topv[b * 2], tv1 = g_topv[b * 2 + 1];
    const float* b2e0 = b2 + (size_t)e0 * Dd + d0;
    const float* b2e1 = b2 + (size_t)e1 * Dd + d0;
    int lrow = lane >> 2;
    int lcol = (lane & 3) * 2;
#pragma unroll
    for (int mt = 0; mt < 2; mt++) {
#pragma unroll
        for (int nt = 0; nt < 8; nt++) {
            int nn = wn * 64 + nt * 8 + lcol;
            float bias0 = tv0 * b2e0[nn]     + tv1 * b2e1[nn];
            float bias1 = tv0 * b2e0[nn + 1] + tv1 * b2e1[nn + 1];
#pragma unroll
            for (int half = 0; half < 2; half++) {
                int s = s0 + wm * 32 + mt * 16 + lrow + half * 8;
                float2 o;
                o.x = d[mt][nt][2 * half]     + bias0;
                o.y = d[mt][nt][2 * half + 1] + bias1;
                *(float2*)(g_mixed + ((size_t)b * Ss + s) * Dd + d0 + nn) = o;
            }
        }
    }
}

// ======================= kernel: out = x + LN(mixed) =======================
__global__ void ln_kernel(const float* __restrict__ x,
                          const float* __restrict__ gamma,
                          const float* __restrict__ beta,
                          float* __restrict__ out) {
    int row = blockIdx.x;
    int tid = threadIdx.x;
    const float* m = g_mixed + (size_t)row * Dd;

    float v0 = m[tid], v1 = m[tid + 256], v2 = m[tid + 512];
    __shared__ float red[256], red2[256];
    red[tid]  = v0 + v1 + v2;
    red2[tid] = v0 * v0 + v1 * v1 + v2 * v2;
    __syncthreads();
    for (int s = 128; s > 0; s >>= 1) {
        if (tid < s) { red[tid] += red[tid + s]; red2[tid] += red2[tid + s]; }
        __syncthreads();
    }
    __shared__ float smu, sinv;
    if (tid == 0) {
        float mu  = red[0] * (1.0f / Dd);
        float var = red2[0] * (1.0f / Dd) - mu * mu;
        smu = mu; sinv = rsqrtf(var + 1e-5f);
    }
    __syncthreads();
    float mu = smu, inv = sinv;
    const float* xr = x + (size_t)row * Dd;
    float* o = out + (size_t)row * Dd;
#pragma unroll
    for (int q = 0; q < 3; q++) {
        int dd = tid + q * 256;
        float mv = m[dd];
        o[dd] = xr[dd] + (mv - mu) * inv * gamma[dd] + beta[dd];
    }
}

// ======================= launch =======================
extern "C" void kernel_launch(void* const* d_in, const int* in_sizes, int n_in,
                              void* d_out, int out_size) {
    const float* x   = (const float*)d_in[0];
    const float* ts  = (const float*)d_in[1];
    const float* W1  = (const float*)d_in[2];
    const float* b1  = (const float*)d_in[3];
    const float* W2  = (const float*)d_in[4];
    const float* b2  = (const float*)d_in[5];
    const float* rw  = (const float*)d_in[6];
    const float* rb  = (const float*)d_in[7];
    const float* gam = (const float*)d_in[8];
    const float* bet = (const float*)d_in[9];

    float* out   = (float*)d_out;
    float* probs = out + (size_t)Bb * Ss * Dd;

    static int configured = 0;
    if (!configured) {
        cudaFuncSetAttribute(gemm1_mma, cudaFuncAttributeMaxDynamicSharedMemorySize, SMEM_BYTES);
        cudaFuncSetAttribute(gemm2_mma, cudaFuncAttributeMaxDynamicSharedMemorySize, SMEM_BYTES);
        configured = 1;
    }

    router_kernel<<<Bb, 256>>>(x, ts, rw, rb, probs);
    split_x_kernel<<<(Bb * Ss * Dd) / 1024, 256>>>(x);
    split_w_kernel<<<dim3(FFf / 32, Dd / 32, Ee), dim3(32, 8)>>>(W1, 0, Dd, FFf);
    split_w_kernel<<<dim3(Dd / 32, FFf / 32, Ee), dim3(32, 8)>>>(W2, 1, FFf, Dd);

    gemm1_mma<<<dim3(FFf / 128, Ss / 128, Bb * KK), 256, SMEM_BYTES>>>(b1);
    gemm2_mma<<<dim3(Dd / 128, Ss / 128, Bb), 256, SMEM_BYTES>>>(b2);

    ln_kernel<<<Bb * Ss, 256>>>(x, gam, bet, out);
}

// round 5
// speedup vs baseline: 3.0519x; 1.2266x over previous
#include <cuda_runtime.h>
#include <cuda_bf16.h>
#include <math.h>
#include <stdint.h>

#define Bb 8
#define Ss 1024
#define Dd 768
#define FFf 3072
#define Ee 8
#define KK 2

// ======================= scratch (no allocs allowed) =======================
__device__ __align__(256) __nv_bfloat16 g_xh[(size_t)Bb * Ss * Dd];
__device__ __align__(256) __nv_bfloat16 g_xl[(size_t)Bb * Ss * Dd];
__device__ __align__(256) __nv_bfloat16 g_w1h[(size_t)Ee * FFf * Dd];   // W1^T [E,FF,D]
__device__ __align__(256) __nv_bfloat16 g_w1l[(size_t)Ee * FFf * Dd];
__device__ __align__(256) __nv_bfloat16 g_w2h[(size_t)Ee * Dd * FFf];   // W2^T [E,D,FF]
__device__ __align__(256) __nv_bfloat16 g_w2l[(size_t)Ee * Dd * FFf];
__device__ __align__(256) __nv_bfloat16 g_hh[(size_t)Bb * KK * Ss * FFf]; // topv*gelu hi
__device__ __align__(256) __nv_bfloat16 g_hl[(size_t)Bb * KK * Ss * FFf]; // lo
__device__ __align__(256) float g_mix0[(size_t)Bb * Ss * Dd];
__device__ __align__(256) float g_mix1[(size_t)Bb * Ss * Dd];
__device__ int   g_topi[Bb * KK];
__device__ float g_topv[Bb * KK];

// ======================= PTX helpers (base ISA sm_80-era) =======================
__device__ __forceinline__ uint32_t smem_u32(const void* p) {
    uint32_t a;
    asm("{ .reg .u64 t; cvta.to.shared.u64 t, %1; cvt.u32.u64 %0, t; }"
        : "=r"(a) : "l"(p));
    return a;
}
__device__ __forceinline__ void cp16(uint32_t s, const void* g) {
    asm volatile("cp.async.cg.shared.global [%0], [%1], 16;" :: "r"(s), "l"(g) : "memory");
}
#define CP_COMMIT() asm volatile("cp.async.commit_group;" ::: "memory")
#define CP_WAIT1()  asm volatile("cp.async.wait_group 1;" ::: "memory")
#define CP_WAIT0()  asm volatile("cp.async.wait_group 0;" ::: "memory")

#define LDSM4(r, addr) \
    asm volatile("ldmatrix.sync.aligned.m8n8.x4.shared.b16 {%0,%1,%2,%3}, [%4];" \
        : "=r"((r)[0]), "=r"((r)[1]), "=r"((r)[2]), "=r"((r)[3]) : "r"(addr))

__device__ __forceinline__ void mma16816(float* d, const uint32_t* a, const uint32_t* b) {
    asm volatile(
        "mma.sync.aligned.m16n8k16.row.col.f32.bf16.bf16.f32 "
        "{%0,%1,%2,%3}, {%4,%5,%6,%7}, {%8,%9}, {%0,%1,%2,%3};"
        : "+f"(d[0]), "+f"(d[1]), "+f"(d[2]), "+f"(d[3])
        : "r"(a[0]), "r"(a[1]), "r"(a[2]), "r"(a[3]), "r"(b[0]), "r"(b[1]));
}

__device__ __forceinline__ float gelu_tanh(float v) {
    float v3 = v * v * v;
    float t  = tanhf(0.7978845608028654f * (v + 0.044715f * v3));
    return 0.5f * v * (1.f + t);
}

// smem tile geometry: 128 rows x 32 bf16, rows padded to 40 bf16 (80B)
#define ROWB  80
#define ARRB  10240                 // 128 * 80
#define STAGE 40960                 // 4 arrays (Ah, Al, Bh, Bl)
#define SMEM_BYTES (2 * STAGE)

// load one stage with 128 threads: A (128x32) hi/lo + B (128x32) hi/lo
__device__ __forceinline__ void load_stage(uint32_t sbase,
                                           const __nv_bfloat16* Ah, const __nv_bfloat16* Al, size_t ldA,
                                           const __nv_bfloat16* Bh, const __nv_bfloat16* Bl, size_t ldB,
                                           int tid) {
#pragma unroll
    for (int i = 0; i < 4; i++) {
        int c   = tid + i * 128;          // 0..511
        int row = c >> 2, q = c & 3;
        uint32_t so = (uint32_t)(row * ROWB + q * 16);
        size_t goA = (size_t)row * ldA + q * 8;
        size_t goB = (size_t)row * ldB + q * 8;
        cp16(sbase + so,            Ah + goA);
        cp16(sbase + ARRB + so,     Al + goA);
        cp16(sbase + 2 * ARRB + so, Bh + goB);
        cp16(sbase + 3 * ARRB + so, Bl + goB);
    }
}

// compute one K=32 stage, warp tile 64M x 64N: D += Ah*Bh + Ah*Bl + Al*Bh
__device__ __forceinline__ void compute_stage(uint32_t sbase, int wm, int wn, int lane,
                                              float d[4][8][4]) {
#pragma unroll
    for (int kb = 0; kb < 2; kb++) {
        uint32_t ah[4][4], al[4][4];
#pragma unroll
        for (int mt = 0; mt < 4; mt++) {
            int row  = wm * 64 + mt * 16 + (lane & 15);
            int kcol = kb * 16 + (lane >> 4) * 8;
            uint32_t ad = sbase + row * ROWB + kcol * 2;
            LDSM4(ah[mt], ad);
            LDSM4(al[mt], ad + ARRB);
        }
        uint32_t bh[8][2], bl[8][2];
#pragma unroll
        for (int p = 0; p < 4; p++) {
            int n    = wn * 64 + p * 16 + ((lane >> 4) & 1) * 8 + (lane & 7);
            int kcol = kb * 16 + ((lane >> 3) & 1) * 8;
            uint32_t bd = sbase + 2 * ARRB + n * ROWB + kcol * 2;
            uint32_t r[4];
            LDSM4(r, bd);
            bh[2 * p][0] = r[0]; bh[2 * p][1] = r[1];
            bh[2 * p + 1][0] = r[2]; bh[2 * p + 1][1] = r[3];
            LDSM4(r, bd + ARRB);
            bl[2 * p][0] = r[0]; bl[2 * p][1] = r[1];
            bl[2 * p + 1][0] = r[2]; bl[2 * p + 1][1] = r[3];
        }
#pragma unroll
        for (int mt = 0; mt < 4; mt++)
#pragma unroll
            for (int nt = 0; nt < 8; nt++) {
                mma16816(d[mt][nt], ah[mt], bh[nt]);
                mma16816(d[mt][nt], ah[mt], bl[nt]);
                mma16816(d[mt][nt], al[mt], bh[nt]);
            }
    }
}

// ======================= kernel: router =======================
__global__ void router_kernel(const float* __restrict__ x,
                              const float* __restrict__ ts,
                              const float* __restrict__ rw,
                              const float* __restrict__ rb,
                              float* __restrict__ probs_out) {
    int b   = blockIdx.x;
    int tid = threadIdx.x;
    __shared__ float feat[2 * Dd];
    for (int d = tid; d < Dd; d += 256) {
        float acc = 0.f;
        const float* xb = x + (size_t)b * Ss * Dd + d;
        for (int s = 0; s < Ss; s++) acc += xb[(size_t)s * Dd];
        feat[d]      = acc * (1.0f / Ss);
        feat[Dd + d] = ts[b * Dd + d];
    }
    __syncthreads();

    __shared__ float red[256];
    __shared__ float logits[Ee];
    for (int e = 0; e < Ee; e++) {
        float p = 0.f;
        for (int d = tid; d < 2 * Dd; d += 256) p += feat[d] * rw[d * Ee + e];
        red[tid] = p;
        __syncthreads();
        for (int s = 128; s > 0; s >>= 1) {
            if (tid < s) red[tid] += red[tid + s];
            __syncthreads();
        }
        if (tid == 0) logits[e] = red[0] + rb[e];
        __syncthreads();
    }

    if (tid == 0) {
        float mx = logits[0];
        for (int e = 1; e < Ee; e++) mx = fmaxf(mx, logits[e]);
        float p[Ee], den = 0.f;
        for (int e = 0; e < Ee; e++) { p[e] = expf(logits[e] - mx); den += p[e]; }
        float inv = 1.f / den;
        for (int e = 0; e < Ee; e++) { p[e] *= inv; probs_out[b * Ee + e] = p[e]; }
        int i0 = 0;
        for (int e = 1; e < Ee; e++) if (p[e] > p[i0]) i0 = e;
        int i1 = -1;
        for (int e = 0; e < Ee; e++) {
            if (e == i0) continue;
            if (i1 < 0 || p[e] > p[i1]) i1 = e;
        }
        g_topi[b * KK + 0] = i0;  g_topv[b * KK + 0] = p[i0];
        g_topi[b * KK + 1] = i1;  g_topv[b * KK + 1] = p[i1];
    }
}

// ======================= kernel: split x into bf16 hi/lo =======================
__global__ void split_x_kernel(const float* __restrict__ x) {
    size_t i = ((size_t)blockIdx.x * blockDim.x + threadIdx.x) * 4;
    float4 v = *(const float4*)(x + i);
    float vv[4] = {v.x, v.y, v.z, v.w};
    __nv_bfloat16 h[4], l[4];
#pragma unroll
    for (int j = 0; j < 4; j++) {
        h[j] = __float2bfloat16_rn(vv[j]);
        l[j] = __float2bfloat16_rn(vv[j] - __bfloat162float(h[j]));
    }
    __nv_bfloat162 h01 = __halves2bfloat162(h[0], h[1]);
    __nv_bfloat162 h23 = __halves2bfloat162(h[2], h[3]);
    __nv_bfloat162 l01 = __halves2bfloat162(l[0], l[1]);
    __nv_bfloat162 l23 = __halves2bfloat162(l[2], l[3]);
    uint2 uh, ul;
    uh.x = *(uint32_t*)&h01; uh.y = *(uint32_t*)&h23;
    ul.x = *(uint32_t*)&l01; ul.y = *(uint32_t*)&l23;
    *(uint2*)(g_xh + i) = uh;
    *(uint2*)(g_xl + i) = ul;
}

// ======================= kernel: transpose + split W =======================
__global__ void split_w_kernel(const float* __restrict__ W, int which, int R, int C) {
    __shared__ float t[32][33];
    int e  = blockIdx.z;
    int c0 = blockIdx.x * 32, r0 = blockIdx.y * 32;
    const float* Wp = W + (size_t)e * R * C;
#pragma unroll
    for (int i = 0; i < 4; i++) {
        int r = r0 + threadIdx.y + i * 8;
        t[threadIdx.y + i * 8][threadIdx.x] = Wp[(size_t)r * C + c0 + threadIdx.x];
    }
    __syncthreads();
    __nv_bfloat16* th = which ? g_w2h : g_w1h;
    __nv_bfloat16* tl = which ? g_w2l : g_w1l;
#pragma unroll
    for (int i = 0; i < 4; i++) {
        int c = c0 + threadIdx.y + i * 8;
        float v = t[threadIdx.x][threadIdx.y + i * 8];
        __nv_bfloat16 h = __float2bfloat16_rn(v);
        __nv_bfloat16 l = __float2bfloat16_rn(v - __bfloat162float(h));
        size_t o = ((size_t)e * C + c) * R + r0 + threadIdx.x;
        th[o] = h; tl[o] = l;
    }
}

// ======================= GEMM1: h = topv * gelu(x W1 + b1) =======================
// grid (FFf/128, Ss/128, B*K), 128 threads, CTA tile 128x128, warp tile 64x64
__global__ __launch_bounds__(128, 2) void gemm1_mma(const float* __restrict__ b1) {
    extern __shared__ char smraw[];
    uint32_t sb = smem_u32(smraw);

    int tid = threadIdx.x, lane = tid & 31, warp = tid >> 5;
    int wm = warp & 1, wn = warp >> 1;
    int bk = blockIdx.z;
    int b  = bk >> 1;
    int e  = g_topi[bk];
    int s0 = blockIdx.y * 128, f0 = blockIdx.x * 128;

    const __nv_bfloat16* Ah = g_xh  + ((size_t)b * Ss + s0) * Dd;
    const __nv_bfloat16* Al = g_xl  + ((size_t)b * Ss + s0) * Dd;
    const __nv_bfloat16* Bh = g_w1h + ((size_t)e * FFf + f0) * Dd;
    const __nv_bfloat16* Bl = g_w1l + ((size_t)e * FFf + f0) * Dd;

    float d[4][8][4];
#pragma unroll
    for (int mt = 0; mt < 4; mt++)
#pragma unroll
        for (int nt = 0; nt < 8; nt++)
#pragma unroll
            for (int q = 0; q < 4; q++) d[mt][nt][q] = 0.f;

    const int nk = Dd / 32;    // 24
    load_stage(sb, Ah, Al, Dd, Bh, Bl, Dd, tid);
    CP_COMMIT();

    for (int ks = 0; ks < nk; ks++) {
        uint32_t buf = (ks & 1) ? sb + STAGE : sb;
        if (ks + 1 < nk) {
            int kk = (ks + 1) * 32;
            uint32_t nbuf = ((ks + 1) & 1) ? sb + STAGE : sb;
            load_stage(nbuf, Ah + kk, Al + kk, Dd, Bh + kk, Bl + kk, Dd, tid);
            CP_COMMIT();
            CP_WAIT1();
        } else {
            CP_WAIT0();
        }
        __syncthreads();
        compute_stage(buf, wm, wn, lane, d);
        __syncthreads();
    }

    // epilogue: + b1, gelu, * topv, split to bf16 hi/lo
    const float* b1e = b1 + (size_t)e * FFf + f0;
    float w = g_topv[bk];
    int lrow = lane >> 2;
    int lcol = (lane & 3) * 2;
#pragma unroll
    for (int mt = 0; mt < 4; mt++) {
#pragma unroll
        for (int nt = 0; nt < 8; nt++) {
            int fc = wn * 64 + nt * 8 + lcol;
            float bb0 = b1e[fc];
            float bb1 = b1e[fc + 1];
#pragma unroll
            for (int half = 0; half < 2; half++) {
                int s = s0 + wm * 64 + mt * 16 + lrow + half * 8;
                float g0 = w * gelu_tanh(d[mt][nt][2 * half]     + bb0);
                float g1 = w * gelu_tanh(d[mt][nt][2 * half + 1] + bb1);
                __nv_bfloat16 h0 = __float2bfloat16_rn(g0);
                __nv_bfloat16 h1 = __float2bfloat16_rn(g1);
                __nv_bfloat16 l0 = __float2bfloat16_rn(g0 - __bfloat162float(h0));
                __nv_bfloat16 l1 = __float2bfloat16_rn(g1 - __bfloat162float(h1));
                __nv_bfloat162 hh = __halves2bfloat162(h0, h1);
                __nv_bfloat162 ll = __halves2bfloat162(l0, l1);
                size_t off = ((size_t)bk * Ss + s) * FFf + f0 + fc;
                *(uint32_t*)(g_hh + off) = *(uint32_t*)&hh;
                *(uint32_t*)(g_hl + off) = *(uint32_t*)&ll;
            }
        }
    }
}

// ======================= GEMM2 (expert-split): y_k = h_k W2[e_k] + topv_k b2[e_k] =======================
// grid (Dd/128, Ss/128, B*K), 128 threads; k=0 writes g_mix0, k=1 writes g_mix1
__global__ __launch_bounds__(128, 2) void gemm2_mma(const float* __restrict__ b2) {
    extern __shared__ char smraw[];
    uint32_t sb = smem_u32(smraw);

    int tid = threadIdx.x, lane = tid & 31, warp = tid >> 5;
    int wm = warp & 1, wn = warp >> 1;
    int bk = blockIdx.z;
    int b  = bk >> 1;
    int e  = g_topi[bk];
    int s0 = blockIdx.y * 128, d0 = blockIdx.x * 128;

    const __nv_bfloat16* Ah = g_hh  + ((size_t)bk * Ss + s0) * FFf;
    const __nv_bfloat16* Al = g_hl  + ((size_t)bk * Ss + s0) * FFf;
    const __nv_bfloat16* Bh = g_w2h + ((size_t)e * Dd + d0) * FFf;
    const __nv_bfloat16* Bl = g_w2l + ((size_t)e * Dd + d0) * FFf;

    float d[4][8][4];
#pragma unroll
    for (int mt = 0; mt < 4; mt++)
#pragma unroll
        for (int nt = 0; nt < 8; nt++)
#pragma unroll
            for (int q = 0; q < 4; q++) d[mt][nt][q] = 0.f;

    const int nk = FFf / 32;   // 96
    load_stage(sb, Ah, Al, FFf, Bh, Bl, FFf, tid);
    CP_COMMIT();

    for (int ks = 0; ks < nk; ks++) {
        uint32_t buf = (ks & 1) ? sb + STAGE : sb;
        if (ks + 1 < nk) {
            int kk = (ks + 1) * 32;
            uint32_t nbuf = ((ks + 1) & 1) ? sb + STAGE : sb;
            load_stage(nbuf, Ah + kk, Al + kk, FFf, Bh + kk, Bl + kk, FFf, tid);
            CP_COMMIT();
            CP_WAIT1();
        } else {
            CP_WAIT0();
        }
        __syncthreads();
        compute_stage(buf, wm, wn, lane, d);
        __syncthreads();
    }

    // epilogue: + topv * b2[e], write fp32 partial
    float tv = g_topv[bk];
    const float* b2e = b2 + (size_t)e * Dd + d0;
    float* dst = (bk & 1) ? g_mix1 : g_mix0;
    int lrow = lane >> 2;
    int lcol = (lane & 3) * 2;
#pragma unroll
    for (int mt = 0; mt < 4; mt++) {
#pragma unroll
        for (int nt = 0; nt < 8; nt++) {
            int nn = wn * 64 + nt * 8 + lcol;
            float bias0 = tv * b2e[nn];
            float bias1 = tv * b2e[nn + 1];
#pragma unroll
            for (int half = 0; half < 2; half++) {
                int s = s0 + wm * 64 + mt * 16 + lrow + half * 8;
                float2 o;
                o.x = d[mt][nt][2 * half]     + bias0;
                o.y = d[mt][nt][2 * half + 1] + bias1;
                *(float2*)(dst + ((size_t)b * Ss + s) * Dd + d0 + nn) = o;
            }
        }
    }
}

// ======================= kernel: out = x + LN(mix0 + mix1) =======================
__global__ void ln_kernel(const float* __restrict__ x,
                          const float* __restrict__ gamma,
                          const float* __restrict__ beta,
                          float* __restrict__ out) {
    int row = blockIdx.x;
    int tid = threadIdx.x;
    const float* m0 = g_mix0 + (size_t)row * Dd;
    const float* m1 = g_mix1 + (size_t)row * Dd;

    float v0 = m0[tid]       + m1[tid];
    float v1 = m0[tid + 256] + m1[tid + 256];
    float v2 = m0[tid + 512] + m1[tid + 512];
    __shared__ float red[256], red2[256];
    red[tid]  = v0 + v1 + v2;
    red2[tid] = v0 * v0 + v1 * v1 + v2 * v2;
    __syncthreads();
    for (int s = 128; s > 0; s >>= 1) {
        if (tid < s) { red[tid] += red[tid + s]; red2[tid] += red2[tid + s]; }
        __syncthreads();
    }
    __shared__ float smu, sinv;
    if (tid == 0) {
        float mu  = red[0] * (1.0f / Dd);
        float var = red2[0] * (1.0f / Dd) - mu * mu;
        smu = mu; sinv = rsqrtf(var + 1e-5f);
    }
    __syncthreads();
    float mu = smu, inv = sinv;
    const float* xr = x + (size_t)row * Dd;
    float* o = out + (size_t)row * Dd;
    float vv[3] = {v0, v1, v2};
#pragma unroll
    for (int q = 0; q < 3; q++) {
        int dd = tid + q * 256;
        o[dd] = xr[dd] + (vv[q] - mu) * inv * gamma[dd] + beta[dd];
    }
}

// ======================= launch =======================
extern "C" void kernel_launch(void* const* d_in, const int* in_sizes, int n_in,
                              void* d_out, int out_size) {
    const float* x   = (const float*)d_in[0];
    const float* ts  = (const float*)d_in[1];
    const float* W1  = (const float*)d_in[2];
    const float* b1  = (const float*)d_in[3];
    const float* W2  = (const float*)d_in[4];
    const float* b2  = (const float*)d_in[5];
    const float* rw  = (const float*)d_in[6];
    const float* rb  = (const float*)d_in[7];
    const float* gam = (const float*)d_in[8];
    const float* bet = (const float*)d_in[9];

    float* out   = (float*)d_out;
    float* probs = out + (size_t)Bb * Ss * Dd;

    cudaFuncSetAttribute(gemm1_mma, cudaFuncAttributeMaxDynamicSharedMemorySize, SMEM_BYTES);
    cudaFuncSetAttribute(gemm2_mma, cudaFuncAttributeMaxDynamicSharedMemorySize, SMEM_BYTES);

    router_kernel<<<Bb, 256>>>(x, ts, rw, rb, probs);
    split_x_kernel<<<(Bb * Ss * Dd) / 1024, 256>>>(x);
    split_w_kernel<<<dim3(FFf / 32, Dd / 32, Ee), dim3(32, 8)>>>(W1, 0, Dd, FFf);
    split_w_kernel<<<dim3(Dd / 32, FFf / 32, Ee), dim3(32, 8)>>>(W2, 1, FFf, Dd);

    gemm1_mma<<<dim3(FFf / 128, Ss / 128, Bb * KK), 128, SMEM_BYTES>>>(b1);
    gemm2_mma<<<dim3(Dd / 128, Ss / 128, Bb * KK), 128, SMEM_BYTES>>>(b2);

    ln_kernel<<<Bb * Ss, 256>>>(x, gam, bet, out);
}

// round 6
// speedup vs baseline: 3.1670x; 1.0377x over previous
#include <cuda_runtime.h>
#include <cuda_bf16.h>
#include <math.h>
#include <stdint.h>

#define Bb 8
#define Ss 1024
#define Dd 768
#define FFf 3072
#define Ee 8
#define KK 2

// ======================= scratch (no allocs allowed) =======================
__device__ __align__(256) __nv_bfloat16 g_xh[(size_t)Bb * Ss * Dd];
__device__ __align__(256) __nv_bfloat16 g_xl[(size_t)Bb * Ss * Dd];
__device__ __align__(256) __nv_bfloat16 g_w1h[(size_t)Ee * FFf * Dd];   // W1^T [E,FF,D]
__device__ __align__(256) __nv_bfloat16 g_w1l[(size_t)Ee * FFf * Dd];
__device__ __align__(256) __nv_bfloat16 g_w2h[(size_t)Ee * Dd * FFf];   // W2^T [E,D,FF]
__device__ __align__(256) __nv_bfloat16 g_w2l[(size_t)Ee * Dd * FFf];
__device__ __align__(256) __nv_bfloat16 g_hh[(size_t)Bb * KK * Ss * FFf]; // topv*gelu hi
__device__ __align__(256) __nv_bfloat16 g_hl[(size_t)Bb * KK * Ss * FFf]; // lo
__device__ __align__(256) float g_mixp[(size_t)4 * Bb * Ss * Dd];         // 4 partials
__device__ int   g_topi[Bb * KK];
__device__ float g_topv[Bb * KK];

// ======================= PTX helpers (base ISA sm_80-era) =======================
__device__ __forceinline__ uint32_t smem_u32(const void* p) {
    uint32_t a;
    asm("{ .reg .u64 t; cvta.to.shared.u64 t, %1; cvt.u32.u64 %0, t; }"
        : "=r"(a) : "l"(p));
    return a;
}
__device__ __forceinline__ void cp16(uint32_t s, const void* g) {
    asm volatile("cp.async.cg.shared.global [%0], [%1], 16;" :: "r"(s), "l"(g) : "memory");
}
#define CP_COMMIT() asm volatile("cp.async.commit_group;" ::: "memory")
#define CP_WAIT1()  asm volatile("cp.async.wait_group 1;" ::: "memory")
#define CP_WAIT0()  asm volatile("cp.async.wait_group 0;" ::: "memory")

#define LDSM4(r, addr) \
    asm volatile("ldmatrix.sync.aligned.m8n8.x4.shared.b16 {%0,%1,%2,%3}, [%4];" \
        : "=r"((r)[0]), "=r"((r)[1]), "=r"((r)[2]), "=r"((r)[3]) : "r"(addr))

__device__ __forceinline__ void mma16816(float* d, const uint32_t* a, const uint32_t* b) {
    asm volatile(
        "mma.sync.aligned.m16n8k16.row.col.f32.bf16.bf16.f32 "
        "{%0,%1,%2,%3}, {%4,%5,%6,%7}, {%8,%9}, {%0,%1,%2,%3};"
        : "+f"(d[0]), "+f"(d[1]), "+f"(d[2]), "+f"(d[3])
        : "r"(a[0]), "r"(a[1]), "r"(a[2]), "r"(a[3]), "r"(b[0]), "r"(b[1]));
}

// fast gelu: tanh.approx.f32 (max rel err ~2^-11, far inside 1e-3 budget)
__device__ __forceinline__ float gelu_fast(float v) {
    float u = v * (0.7978845608028654f + 0.035677408136300125f * v * v);
    float t;
    asm("tanh.approx.f32 %0, %1;" : "=f"(t) : "f"(u));
    return 0.5f * v * (1.f + t);
}

// smem tile geometry: 128 rows x 32 bf16, rows padded to 40 bf16 (80B)
#define ROWB  80
#define ARRB  10240                 // 128 * 80
#define STAGE 40960                 // 4 arrays (Ah, Al, Bh, Bl)
#define SMEM_BYTES (2 * STAGE)

// load one stage with 128 threads: A (128x32) hi/lo + B (128x32) hi/lo
__device__ __forceinline__ void load_stage(uint32_t sbase,
                                           const __nv_bfloat16* Ah, const __nv_bfloat16* Al, size_t ldA,
                                           const __nv_bfloat16* Bh, const __nv_bfloat16* Bl, size_t ldB,
                                           int tid) {
#pragma unroll
    for (int i = 0; i < 4; i++) {
        int c   = tid + i * 128;          // 0..511
        int row = c >> 2, q = c & 3;
        uint32_t so = (uint32_t)(row * ROWB + q * 16);
        size_t goA = (size_t)row * ldA + q * 8;
        size_t goB = (size_t)row * ldB + q * 8;
        cp16(sbase + so,            Ah + goA);
        cp16(sbase + ARRB + so,     Al + goA);
        cp16(sbase + 2 * ARRB + so, Bh + goB);
        cp16(sbase + 3 * ARRB + so, Bl + goB);
    }
}

// compute one K=32 stage, warp tile 64M x 64N: D += Ah*Bh + Ah*Bl + Al*Bh
// B fragments double-buffered: ldsm of group p+1 issued before mma burst of group p
__device__ __forceinline__ void compute_stage(uint32_t sbase, int wm, int wn, int lane,
                                              float d[4][8][4]) {
#pragma unroll
    for (int kb = 0; kb < 2; kb++) {
        uint32_t ah[4][4], al[4][4];
#pragma unroll
        for (int mt = 0; mt < 4; mt++) {
            int row  = wm * 64 + mt * 16 + (lane & 15);
            int kcol = kb * 16 + (lane >> 4) * 8;
            uint32_t ad = sbase + row * ROWB + kcol * 2;
            LDSM4(ah[mt], ad);
            LDSM4(al[mt], ad + ARRB);
        }
        int nbase = wn * 64 + ((lane >> 4) & 1) * 8 + (lane & 7);
        int kcol  = kb * 16 + ((lane >> 3) & 1) * 8;
        uint32_t bbase = sbase + 2 * ARRB + kcol * 2;

        uint32_t bh[2][2][2], bl[2][2][2];     // [buf][nt-in-group][reg]
        {   // prime group 0
            uint32_t bd = bbase + (nbase + 0) * ROWB;
            uint32_t r[4];
            LDSM4(r, bd);
            bh[0][0][0] = r[0]; bh[0][0][1] = r[1]; bh[0][1][0] = r[2]; bh[0][1][1] = r[3];
            LDSM4(r, bd + ARRB);
            bl[0][0][0] = r[0]; bl[0][0][1] = r[1]; bl[0][1][0] = r[2]; bl[0][1][1] = r[3];
        }
#pragma unroll
        for (int p = 0; p < 4; p++) {
            int cur = p & 1, nxt = cur ^ 1;
            if (p < 3) {                        // prefetch group p+1
                uint32_t bd = bbase + (nbase + (p + 1) * 16) * ROWB;
                uint32_t r[4];
                LDSM4(r, bd);
                bh[nxt][0][0] = r[0]; bh[nxt][0][1] = r[1];
                bh[nxt][1][0] = r[2]; bh[nxt][1][1] = r[3];
                LDSM4(r, bd + ARRB);
                bl[nxt][0][0] = r[0]; bl[nxt][0][1] = r[1];
                bl[nxt][1][0] = r[2]; bl[nxt][1][1] = r[3];
            }
#pragma unroll
            for (int g = 0; g < 2; g++) {
                int nt = 2 * p + g;
#pragma unroll
                for (int mt = 0; mt < 4; mt++) {
                    mma16816(d[mt][nt], ah[mt], bh[cur][g]);
                    mma16816(d[mt][nt], ah[mt], bl[cur][g]);
                    mma16816(d[mt][nt], al[mt], bh[cur][g]);
                }
            }
        }
    }
}

// ======================= kernel: router =======================
__global__ void router_kernel(const float* __restrict__ x,
                              const float* __restrict__ ts,
                              const float* __restrict__ rw,
                              const float* __restrict__ rb,
                              float* __restrict__ probs_out) {
    int b   = blockIdx.x;
    int tid = threadIdx.x;
    __shared__ float feat[2 * Dd];
    for (int d = tid; d < Dd; d += 256) {
        float acc = 0.f;
        const float* xb = x + (size_t)b * Ss * Dd + d;
        for (int s = 0; s < Ss; s++) acc += xb[(size_t)s * Dd];
        feat[d]      = acc * (1.0f / Ss);
        feat[Dd + d] = ts[b * Dd + d];
    }
    __syncthreads();

    __shared__ float red[256];
    __shared__ float logits[Ee];
    for (int e = 0; e < Ee; e++) {
        float p = 0.f;
        for (int d = tid; d < 2 * Dd; d += 256) p += feat[d] * rw[d * Ee + e];
        red[tid] = p;
        __syncthreads();
        for (int s = 128; s > 0; s >>= 1) {
            if (tid < s) red[tid] += red[tid + s];
            __syncthreads();
        }
        if (tid == 0) logits[e] = red[0] + rb[e];
        __syncthreads();
    }

    if (tid == 0) {
        float mx = logits[0];
        for (int e = 1; e < Ee; e++) mx = fmaxf(mx, logits[e]);
        float p[Ee], den = 0.f;
        for (int e = 0; e < Ee; e++) { p[e] = expf(logits[e] - mx); den += p[e]; }
        float inv = 1.f / den;
        for (int e = 0; e < Ee; e++) { p[e] *= inv; probs_out[b * Ee + e] = p[e]; }
        int i0 = 0;
        for (int e = 1; e < Ee; e++) if (p[e] > p[i0]) i0 = e;
        int i1 = -1;
        for (int e = 0; e < Ee; e++) {
            if (e == i0) continue;
            if (i1 < 0 || p[e] > p[i1]) i1 = e;
        }
        g_topi[b * KK + 0] = i0;  g_topv[b * KK + 0] = p[i0];
        g_topi[b * KK + 1] = i1;  g_topv[b * KK + 1] = p[i1];
    }
}

// ======================= kernel: split x into bf16 hi/lo =======================
__global__ void split_x_kernel(const float* __restrict__ x) {
    size_t i = ((size_t)blockIdx.x * blockDim.x + threadIdx.x) * 4;
    float4 v = *(const float4*)(x + i);
    float vv[4] = {v.x, v.y, v.z, v.w};
    __nv_bfloat16 h[4], l[4];
#pragma unroll
    for (int j = 0; j < 4; j++) {
        h[j] = __float2bfloat16_rn(vv[j]);
        l[j] = __float2bfloat16_rn(vv[j] - __bfloat162float(h[j]));
    }
    __nv_bfloat162 h01 = __halves2bfloat162(h[0], h[1]);
    __nv_bfloat162 h23 = __halves2bfloat162(h[2], h[3]);
    __nv_bfloat162 l01 = __halves2bfloat162(l[0], l[1]);
    __nv_bfloat162 l23 = __halves2bfloat162(l[2], l[3]);
    uint2 uh, ul;
    uh.x = *(uint32_t*)&h01; uh.y = *(uint32_t*)&h23;
    ul.x = *(uint32_t*)&l01; ul.y = *(uint32_t*)&l23;
    *(uint2*)(g_xh + i) = uh;
    *(uint2*)(g_xl + i) = ul;
}

// ======================= kernel: transpose + split W =======================
__global__ void split_w_kernel(const float* __restrict__ W, int which, int R, int C) {
    __shared__ float t[32][33];
    int e  = blockIdx.z;
    int c0 = blockIdx.x * 32, r0 = blockIdx.y * 32;
    const float* Wp = W + (size_t)e * R * C;
#pragma unroll
    for (int i = 0; i < 4; i++) {
        int r = r0 + threadIdx.y + i * 8;
        t[threadIdx.y + i * 8][threadIdx.x] = Wp[(size_t)r * C + c0 + threadIdx.x];
    }
    __syncthreads();
    __nv_bfloat16* th = which ? g_w2h : g_w1h;
    __nv_bfloat16* tl = which ? g_w2l : g_w1l;
#pragma unroll
    for (int i = 0; i < 4; i++) {
        int c = c0 + threadIdx.y + i * 8;
        float v = t[threadIdx.x][threadIdx.y + i * 8];
        __nv_bfloat16 h = __float2bfloat16_rn(v);
        __nv_bfloat16 l = __float2bfloat16_rn(v - __bfloat162float(h));
        size_t o = ((size_t)e * C + c) * R + r0 + threadIdx.x;
        th[o] = h; tl[o] = l;
    }
}

// ======================= GEMM1: h = topv * gelu(x W1 + b1) =======================
// grid (FFf/128, Ss/128, B*K), 128 threads, CTA tile 128x128, warp tile 64x64
__global__ __launch_bounds__(128, 2) void gemm1_mma(const float* __restrict__ b1) {
    extern __shared__ char smraw[];
    uint32_t sb = smem_u32(smraw);

    int tid = threadIdx.x, lane = tid & 31, warp = tid >> 5;
    int wm = warp & 1, wn = warp >> 1;
    int bk = blockIdx.z;
    int b  = bk >> 1;
    int e  = g_topi[bk];
    int s0 = blockIdx.y * 128, f0 = blockIdx.x * 128;

    const __nv_bfloat16* Ah = g_xh  + ((size_t)b * Ss + s0) * Dd;
    const __nv_bfloat16* Al = g_xl  + ((size_t)b * Ss + s0) * Dd;
    const __nv_bfloat16* Bh = g_w1h + ((size_t)e * FFf + f0) * Dd;
    const __nv_bfloat16* Bl = g_w1l + ((size_t)e * FFf + f0) * Dd;

    float d[4][8][4];
#pragma unroll
    for (int mt = 0; mt < 4; mt++)
#pragma unroll
        for (int nt = 0; nt < 8; nt++)
#pragma unroll
            for (int q = 0; q < 4; q++) d[mt][nt][q] = 0.f;

    const int nk = Dd / 32;    // 24
    load_stage(sb, Ah, Al, Dd, Bh, Bl, Dd, tid);
    CP_COMMIT();

    for (int ks = 0; ks < nk; ks++) {
        uint32_t buf = (ks & 1) ? sb + STAGE : sb;
        if (ks + 1 < nk) {
            int kk = (ks + 1) * 32;
            uint32_t nbuf = ((ks + 1) & 1) ? sb + STAGE : sb;
            load_stage(nbuf, Ah + kk, Al + kk, Dd, Bh + kk, Bl + kk, Dd, tid);
            CP_COMMIT();
            CP_WAIT1();
        } else {
            CP_WAIT0();
        }
        __syncthreads();
        compute_stage(buf, wm, wn, lane, d);
        __syncthreads();
    }

    // epilogue: + b1, gelu, * topv, split to bf16 hi/lo
    const float* b1e = b1 + (size_t)e * FFf + f0;
    float w = g_topv[bk];
    int lrow = lane >> 2;
    int lcol = (lane & 3) * 2;
#pragma unroll
    for (int mt = 0; mt < 4; mt++) {
#pragma unroll
        for (int nt = 0; nt < 8; nt++) {
            int fc = wn * 64 + nt * 8 + lcol;
            float bb0 = b1e[fc];
            float bb1 = b1e[fc + 1];
#pragma unroll
            for (int half = 0; half < 2; half++) {
                int s = s0 + wm * 64 + mt * 16 + lrow + half * 8;
                float g0 = w * gelu_fast(d[mt][nt][2 * half]     + bb0);
                float g1 = w * gelu_fast(d[mt][nt][2 * half + 1] + bb1);
                __nv_bfloat16 h0 = __float2bfloat16_rn(g0);
                __nv_bfloat16 h1 = __float2bfloat16_rn(g1);
                __nv_bfloat16 l0 = __float2bfloat16_rn(g0 - __bfloat162float(h0));
                __nv_bfloat16 l1 = __float2bfloat16_rn(g1 - __bfloat162float(h1));
                __nv_bfloat162 hh = __halves2bfloat162(h0, h1);
                __nv_bfloat162 ll = __halves2bfloat162(l0, l1);
                size_t off = ((size_t)bk * Ss + s) * FFf + f0 + fc;
                *(uint32_t*)(g_hh + off) = *(uint32_t*)&hh;
                *(uint32_t*)(g_hl + off) = *(uint32_t*)&ll;
            }
        }
    }
}

// ======================= GEMM2 (expert- and K-split) =======================
// grid (Dd/128, Ss/128, B*K*2), 128 threads; z = bk*2 + slice (slice = half of FF)
// partial (bk&1)*2+slice written to g_mixp; bias added only on slice 0
__global__ __launch_bounds__(128, 2) void gemm2_mma(const float* __restrict__ b2) {
    extern __shared__ char smraw[];
    uint32_t sb = smem_u32(smraw);

    int tid = threadIdx.x, lane = tid & 31, warp = tid >> 5;
    int wm = warp & 1, wn = warp >> 1;
    int z     = blockIdx.z;
    int bk    = z >> 1;
    int slice = z & 1;
    int b  = bk >> 1;
    int e  = g_topi[bk];
    int s0 = blockIdx.y * 128, d0 = blockIdx.x * 128;
    int kbase = slice * (FFf / 2);

    const __nv_bfloat16* Ah = g_hh  + ((size_t)bk * Ss + s0) * FFf + kbase;
    const __nv_bfloat16* Al = g_hl  + ((size_t)bk * Ss + s0) * FFf + kbase;
    const __nv_bfloat16* Bh = g_w2h + ((size_t)e * Dd + d0) * FFf + kbase;
    const __nv_bfloat16* Bl = g_w2l + ((size_t)e * Dd + d0) * FFf + kbase;

    float d[4][8][4];
#pragma unroll
    for (int mt = 0; mt < 4; mt++)
#pragma unroll
        for (int nt = 0; nt < 8; nt++)
#pragma unroll
            for (int q = 0; q < 4; q++) d[mt][nt][q] = 0.f;

    const int nk = (FFf / 2) / 32;   // 48
    load_stage(sb, Ah, Al, FFf, Bh, Bl, FFf, tid);
    CP_COMMIT();

    for (int ks = 0; ks < nk; ks++) {
        uint32_t buf = (ks & 1) ? sb + STAGE : sb;
        if (ks + 1 < nk) {
            int kk = (ks + 1) * 32;
            uint32_t nbuf = ((ks + 1) & 1) ? sb + STAGE : sb;
            load_stage(nbuf, Ah + kk, Al + kk, FFf, Bh + kk, Bl + kk, FFf, tid);
            CP_COMMIT();
            CP_WAIT1();
        } else {
            CP_WAIT0();
        }
        __syncthreads();
        compute_stage(buf, wm, wn, lane, d);
        __syncthreads();
    }

    // epilogue: + topv * b2[e] (slice 0 only), write fp32 partial
    float tv = (slice == 0) ? g_topv[bk] : 0.f;
    const float* b2e = b2 + (size_t)e * Dd + d0;
    float* dst = g_mixp + (size_t)((bk & 1) * 2 + slice) * ((size_t)Bb * Ss * Dd);
    int lrow = lane >> 2;
    int lcol = (lane & 3) * 2;
#pragma unroll
    for (int mt = 0; mt < 4; mt++) {
#pragma unroll
        for (int nt = 0; nt < 8; nt++) {
            int nn = wn * 64 + nt * 8 + lcol;
            float bias0 = tv * b2e[nn];
            float bias1 = tv * b2e[nn + 1];
#pragma unroll
            for (int half = 0; half < 2; half++) {
                int s = s0 + wm * 64 + mt * 16 + lrow + half * 8;
                float2 o;
                o.x = d[mt][nt][2 * half]     + bias0;
                o.y = d[mt][nt][2 * half + 1] + bias1;
                *(float2*)(dst + ((size_t)b * Ss + s) * Dd + d0 + nn) = o;
            }
        }
    }
}

// ======================= kernel: out = x + LN(sum of 4 partials) =======================
__global__ void ln_kernel(const float* __restrict__ x,
                          const float* __restrict__ gamma,
                          const float* __restrict__ beta,
                          float* __restrict__ out) {
    int row = blockIdx.x;
    int tid = threadIdx.x;
    const size_t BSD = (size_t)Bb * Ss * Dd;
    const float* m0 = g_mixp + (size_t)row * Dd;
    const float* m1 = m0 + BSD;
    const float* m2 = m1 + BSD;
    const float* m3 = m2 + BSD;

    float v0 = m0[tid]       + m1[tid]       + m2[tid]       + m3[tid];
    float v1 = m0[tid + 256] + m1[tid + 256] + m2[tid + 256] + m3[tid + 256];
    float v2 = m0[tid + 512] + m1[tid + 512] + m2[tid + 512] + m3[tid + 512];
    __shared__ float red[256], red2[256];
    red[tid]  = v0 + v1 + v2;
    red2[tid] = v0 * v0 + v1 * v1 + v2 * v2;
    __syncthreads();
    for (int s = 128; s > 0; s >>= 1) {
        if (tid < s) { red[tid] += red[tid + s]; red2[tid] += red2[tid + s]; }
        __syncthreads();
    }
    __shared__ float smu, sinv;
    if (tid == 0) {
        float mu  = red[0] * (1.0f / Dd);
        float var = red2[0] * (1.0f / Dd) - mu * mu;
        smu = mu; sinv = rsqrtf(var + 1e-5f);
    }
    __syncthreads();
    float mu = smu, inv = sinv;
    const float* xr = x + (size_t)row * Dd;
    float* o = out + (size_t)row * Dd;
    float vv[3] = {v0, v1, v2};
#pragma unroll
    for (int q = 0; q < 3; q++) {
        int dd = tid + q * 256;
        o[dd] = xr[dd] + (vv[q] - mu) * inv * gamma[dd] + beta[dd];
    }
}

// ======================= launch =======================
extern "C" void kernel_launch(void* const* d_in, const int* in_sizes, int n_in,
                              void* d_out, int out_size) {
    const float* x   = (const float*)d_in[0];
    const float* ts  = (const float*)d_in[1];
    const float* W1  = (const float*)d_in[2];
    const float* b1  = (const float*)d_in[3];
    const float* W2  = (const float*)d_in[4];
    const float* b2  = (const float*)d_in[5];
    const float* rw  = (const float*)d_in[6];
    const float* rb  = (const float*)d_in[7];
    const float* gam = (const float*)d_in[8];
    const float* bet = (const float*)d_in[9];

    float* out   = (float*)d_out;
    float* probs = out + (size_t)Bb * Ss * Dd;

    cudaFuncSetAttribute(gemm1_mma, cudaFuncAttributeMaxDynamicSharedMemorySize, SMEM_BYTES);
    cudaFuncSetAttribute(gemm2_mma, cudaFuncAttributeMaxDynamicSharedMemorySize, SMEM_BYTES);

    router_kernel<<<Bb, 256>>>(x, ts, rw, rb, probs);
    split_x_kernel<<<(Bb * Ss * Dd) / 1024, 256>>>(x);
    split_w_kernel<<<dim3(FFf / 32, Dd / 32, Ee), dim3(32, 8)>>>(W1, 0, Dd, FFf);
    split_w_kernel<<<dim3(Dd / 32, FFf / 32, Ee), dim3(32, 8)>>>(W2, 1, FFf, Dd);

    gemm1_mma<<<dim3(FFf / 128, Ss / 128, Bb * KK), 128, SMEM_BYTES>>>(b1);
    gemm2_mma<<<dim3(Dd / 128, Ss / 128, Bb * KK * 2), 128, SMEM_BYTES>>>(b2);

    ln_kernel<<<Bb * Ss, 256>>>(x, gam, bet, out);
}

// round 7
// speedup vs baseline: 3.9515x; 1.2477x over previous
#include <cuda_runtime.h>
#include <cuda_fp16.h>
#include <math.h>
#include <stdint.h>

#define Bb 8
#define Ss 1024
#define Dd 768
#define FFf 3072
#define Ee 8
#define KK 2

// ======================= scratch (no allocs allowed) =======================
__device__ __align__(256) __half g_xh[(size_t)Bb * Ss * Dd];
__device__ __align__(256) __half g_xl[(size_t)Bb * Ss * Dd];
__device__ __align__(256) __half g_w1[(size_t)Ee * FFf * Dd];    // W1^T [E,FF,D] fp16
__device__ __align__(256) __half g_w2[(size_t)Ee * Dd * FFf];    // W2^T [E,D,FF] fp16
__device__ __align__(256) __half g_hh[(size_t)Bb * KK * Ss * FFf]; // topv*gelu hi
__device__ __align__(256) __half g_hl[(size_t)Bb * KK * Ss * FFf]; // lo
__device__ __align__(256) float g_mixp[(size_t)4 * Bb * Ss * Dd];  // 4 partials
__device__ int   g_topi[Bb * KK];
__device__ float g_topv[Bb * KK];

// ======================= PTX helpers (base ISA sm_80-era) =======================
__device__ __forceinline__ uint32_t smem_u32(const void* p) {
    uint32_t a;
    asm("{ .reg .u64 t; cvta.to.shared.u64 t, %1; cvt.u32.u64 %0, t; }"
        : "=r"(a) : "l"(p));
    return a;
}
__device__ __forceinline__ void cp16(uint32_t s, const void* g) {
    asm volatile("cp.async.cg.shared.global [%0], [%1], 16;" :: "r"(s), "l"(g) : "memory");
}
#define CP_COMMIT() asm volatile("cp.async.commit_group;" ::: "memory")
#define CP_WAIT1()  asm volatile("cp.async.wait_group 1;" ::: "memory")
#define CP_WAIT0()  asm volatile("cp.async.wait_group 0;" ::: "memory")

#define LDSM4(r, addr) \
    asm volatile("ldmatrix.sync.aligned.m8n8.x4.shared.b16 {%0,%1,%2,%3}, [%4];" \
        : "=r"((r)[0]), "=r"((r)[1]), "=r"((r)[2]), "=r"((r)[3]) : "r"(addr))

__device__ __forceinline__ void mma16816(float* d, const uint32_t* a, const uint32_t* b) {
    asm volatile(
        "mma.sync.aligned.m16n8k16.row.col.f32.f16.f16.f32 "
        "{%0,%1,%2,%3}, {%4,%5,%6,%7}, {%8,%9}, {%0,%1,%2,%3};"
        : "+f"(d[0]), "+f"(d[1]), "+f"(d[2]), "+f"(d[3])
        : "r"(a[0]), "r"(a[1]), "r"(a[2]), "r"(a[3]), "r"(b[0]), "r"(b[1]));
}

// fast gelu: tanh.approx.f32 (max rel err ~2^-11)
__device__ __forceinline__ float gelu_fast(float v) {
    float u = v * (0.7978845608028654f + 0.035677408136300125f * v * v);
    float t;
    asm("tanh.approx.f32 %0, %1;" : "=f"(t) : "f"(u));
    return 0.5f * v * (1.f + t);
}

// smem tile geometry: 128 rows x 32 fp16, rows padded to 40 halves (80B)
#define ROWB  80
#define ARRB  10240                 // 128 * 80
#define STAGE 30720                 // 3 arrays (Ah, Al, B)
#define SMEM_BYTES (2 * STAGE)

// load one stage with 128 threads: A (128x32) hi/lo + B (128x32)
__device__ __forceinline__ void load_stage(uint32_t sbase,
                                           const __half* Ah, const __half* Al, size_t ldA,
                                           const __half* Bw, size_t ldB,
                                           int tid) {
#pragma unroll
    for (int i = 0; i < 4; i++) {
        int c   = tid + i * 128;          // 0..511
        int row = c >> 2, q = c & 3;
        uint32_t so = (uint32_t)(row * ROWB + q * 16);
        size_t goA = (size_t)row * ldA + q * 8;
        size_t goB = (size_t)row * ldB + q * 8;
        cp16(sbase + so,            Ah + goA);
        cp16(sbase + ARRB + so,     Al + goA);
        cp16(sbase + 2 * ARRB + so, Bw + goB);
    }
}

// compute one K=32 stage, warp tile 64M x 64N: D += Ah*B + Al*B  (2 MMAs)
// B fragments double-buffered across nt-groups
__device__ __forceinline__ void compute_stage(uint32_t sbase, int wm, int wn, int lane,
                                              float d[4][8][4]) {
#pragma unroll
    for (int kb = 0; kb < 2; kb++) {
        uint32_t ah[4][4], al[4][4];
#pragma unroll
        for (int mt = 0; mt < 4; mt++) {
            int row  = wm * 64 + mt * 16 + (lane & 15);
            int kcol = kb * 16 + (lane >> 4) * 8;
            uint32_t ad = sbase + row * ROWB + kcol * 2;
            LDSM4(ah[mt], ad);
            LDSM4(al[mt], ad + ARRB);
        }
        int nbase = wn * 64 + ((lane >> 4) & 1) * 8 + (lane & 7);
        int kcol  = kb * 16 + ((lane >> 3) & 1) * 8;
        uint32_t bbase = sbase + 2 * ARRB + kcol * 2;

        uint32_t bf[2][2][2];                // [buf][nt-in-group][reg]
        {   // prime group 0
            uint32_t r[4];
            LDSM4(r, bbase + nbase * ROWB);
            bf[0][0][0] = r[0]; bf[0][0][1] = r[1];
            bf[0][1][0] = r[2]; bf[0][1][1] = r[3];
        }
#pragma unroll
        for (int p = 0; p < 4; p++) {
            int cur = p & 1, nxt = cur ^ 1;
            if (p < 3) {                     // prefetch group p+1
                uint32_t r[4];
                LDSM4(r, bbase + (nbase + (p + 1) * 16) * ROWB);
                bf[nxt][0][0] = r[0]; bf[nxt][0][1] = r[1];
                bf[nxt][1][0] = r[2]; bf[nxt][1][1] = r[3];
            }
#pragma unroll
            for (int g = 0; g < 2; g++) {
                int nt = 2 * p + g;
#pragma unroll
                for (int mt = 0; mt < 4; mt++) {
                    mma16816(d[mt][nt], ah[mt], bf[cur][g]);
                    mma16816(d[mt][nt], al[mt], bf[cur][g]);
                }
            }
        }
    }
}

// ======================= kernel: router =======================
__global__ void router_kernel(const float* __restrict__ x,
                              const float* __restrict__ ts,
                              const float* __restrict__ rw,
                              const float* __restrict__ rb,
                              float* __restrict__ probs_out) {
    int b   = blockIdx.x;
    int tid = threadIdx.x;
    __shared__ float feat[2 * Dd];
    for (int d = tid; d < Dd; d += 256) {
        float acc = 0.f;
        const float* xb = x + (size_t)b * Ss * Dd + d;
        for (int s = 0; s < Ss; s++) acc += xb[(size_t)s * Dd];
        feat[d]      = acc * (1.0f / Ss);
        feat[Dd + d] = ts[b * Dd + d];
    }
    __syncthreads();

    __shared__ float red[256];
    __shared__ float logits[Ee];
    for (int e = 0; e < Ee; e++) {
        float p = 0.f;
        for (int d = tid; d < 2 * Dd; d += 256) p += feat[d] * rw[d * Ee + e];
        red[tid] = p;
        __syncthreads();
        for (int s = 128; s > 0; s >>= 1) {
            if (tid < s) red[tid] += red[tid + s];
            __syncthreads();
        }
        if (tid == 0) logits[e] = red[0] + rb[e];
        __syncthreads();
    }

    if (tid == 0) {
        float mx = logits[0];
        for (int e = 1; e < Ee; e++) mx = fmaxf(mx, logits[e]);
        float p[Ee], den = 0.f;
        for (int e = 0; e < Ee; e++) { p[e] = expf(logits[e] - mx); den += p[e]; }
        float inv = 1.f / den;
        for (int e = 0; e < Ee; e++) { p[e] *= inv; probs_out[b * Ee + e] = p[e]; }
        int i0 = 0;
        for (int e = 1; e < Ee; e++) if (p[e] > p[i0]) i0 = e;
        int i1 = -1;
        for (int e = 0; e < Ee; e++) {
            if (e == i0) continue;
            if (i1 < 0 || p[e] > p[i1]) i1 = e;
        }
        g_topi[b * KK + 0] = i0;  g_topv[b * KK + 0] = p[i0];
        g_topi[b * KK + 1] = i1;  g_topv[b * KK + 1] = p[i1];
    }
}

// ======================= kernel: split x into fp16 hi/lo =======================
__global__ void split_x_kernel(const float* __restrict__ x) {
    size_t i = ((size_t)blockIdx.x * blockDim.x + threadIdx.x) * 4;
    float4 v = *(const float4*)(x + i);
    float vv[4] = {v.x, v.y, v.z, v.w};
    __half h[4], l[4];
#pragma unroll
    for (int j = 0; j < 4; j++) {
        h[j] = __float2half_rn(vv[j]);
        l[j] = __float2half_rn(vv[j] - __half2float(h[j]));
    }
    __half2 h01 = __halves2half2(h[0], h[1]);
    __half2 h23 = __halves2half2(h[2], h[3]);
    __half2 l01 = __halves2half2(l[0], l[1]);
    __half2 l23 = __halves2half2(l[2], l[3]);
    uint2 uh, ul;
    uh.x = *(uint32_t*)&h01; uh.y = *(uint32_t*)&h23;
    ul.x = *(uint32_t*)&l01; ul.y = *(uint32_t*)&l23;
    *(uint2*)(g_xh + i) = uh;
    *(uint2*)(g_xl + i) = ul;
}

// ======================= kernel: transpose W -> fp16 =======================
// in: W [E, R, C]  ->  out [E, C, R] fp16.  which=0 -> W1, which=1 -> W2
__global__ void split_w_kernel(const float* __restrict__ W, int which, int R, int C) {
    __shared__ float t[32][33];
    int e  = blockIdx.z;
    int c0 = blockIdx.x * 32, r0 = blockIdx.y * 32;
    const float* Wp = W + (size_t)e * R * C;
#pragma unroll
    for (int i = 0; i < 4; i++) {
        int r = r0 + threadIdx.y + i * 8;
        t[threadIdx.y + i * 8][threadIdx.x] = Wp[(size_t)r * C + c0 + threadIdx.x];
    }
    __syncthreads();
    __half* th = which ? g_w2 : g_w1;
#pragma unroll
    for (int i = 0; i < 4; i++) {
        int c = c0 + threadIdx.y + i * 8;
        float v = t[threadIdx.x][threadIdx.y + i * 8];
        size_t o = ((size_t)e * C + c) * R + r0 + threadIdx.x;
        th[o] = __float2half_rn(v);
    }
}

// ======================= GEMM1: h = topv * gelu(x W1 + b1) =======================
// grid (FFf/128, Ss/128, B*K), 128 threads, CTA tile 128x128, warp tile 64x64
__global__ __launch_bounds__(128, 2) void gemm1_mma(const float* __restrict__ b1) {
    extern __shared__ char smraw[];
    uint32_t sb = smem_u32(smraw);

    int tid = threadIdx.x, lane = tid & 31, warp = tid >> 5;
    int wm = warp & 1, wn = warp >> 1;
    int bk = blockIdx.z;
    int b  = bk >> 1;
    int e  = g_topi[bk];
    int s0 = blockIdx.y * 128, f0 = blockIdx.x * 128;

    const __half* Ah = g_xh + ((size_t)b * Ss + s0) * Dd;
    const __half* Al = g_xl + ((size_t)b * Ss + s0) * Dd;
    const __half* Bw = g_w1 + ((size_t)e * FFf + f0) * Dd;

    float d[4][8][4];
#pragma unroll
    for (int mt = 0; mt < 4; mt++)
#pragma unroll
        for (int nt = 0; nt < 8; nt++)
#pragma unroll
            for (int q = 0; q < 4; q++) d[mt][nt][q] = 0.f;

    const int nk = Dd / 32;    // 24
    load_stage(sb, Ah, Al, Dd, Bw, Dd, tid);
    CP_COMMIT();

    for (int ks = 0; ks < nk; ks++) {
        uint32_t buf = (ks & 1) ? sb + STAGE : sb;
        if (ks + 1 < nk) {
            int kk = (ks + 1) * 32;
            uint32_t nbuf = ((ks + 1) & 1) ? sb + STAGE : sb;
            load_stage(nbuf, Ah + kk, Al + kk, Dd, Bw + kk, Dd, tid);
            CP_COMMIT();
            CP_WAIT1();
        } else {
            CP_WAIT0();
        }
        __syncthreads();
        compute_stage(buf, wm, wn, lane, d);
        __syncthreads();
    }

    // epilogue: + b1, gelu, * topv, split to fp16 hi/lo
    const float* b1e = b1 + (size_t)e * FFf + f0;
    float w = g_topv[bk];
    int lrow = lane >> 2;
    int lcol = (lane & 3) * 2;
#pragma unroll
    for (int mt = 0; mt < 4; mt++) {
#pragma unroll
        for (int nt = 0; nt < 8; nt++) {
            int fc = wn * 64 + nt * 8 + lcol;
            float bb0 = b1e[fc];
            float bb1 = b1e[fc + 1];
#pragma unroll
            for (int half_i = 0; half_i < 2; half_i++) {
                int s = s0 + wm * 64 + mt * 16 + lrow + half_i * 8;
                float g0 = w * gelu_fast(d[mt][nt][2 * half_i]     + bb0);
                float g1 = w * gelu_fast(d[mt][nt][2 * half_i + 1] + bb1);
                __half h0 = __float2half_rn(g0);
                __half h1 = __float2half_rn(g1);
                __half l0 = __float2half_rn(g0 - __half2float(h0));
                __half l1 = __float2half_rn(g1 - __half2float(h1));
                __half2 hh = __halves2half2(h0, h1);
                __half2 ll = __halves2half2(l0, l1);
                size_t off = ((size_t)bk * Ss + s) * FFf + f0 + fc;
                *(uint32_t*)(g_hh + off) = *(uint32_t*)&hh;
                *(uint32_t*)(g_hl + off) = *(uint32_t*)&ll;
            }
        }
    }
}

// ======================= GEMM2 (expert- and K-split) =======================
// grid (Dd/128, Ss/128, B*K*2); z = bk*2 + slice (slice = half of FF)
__global__ __launch_bounds__(128, 2) void gemm2_mma(const float* __restrict__ b2) {
    extern __shared__ char smraw[];
    uint32_t sb = smem_u32(smraw);

    int tid = threadIdx.x, lane = tid & 31, warp = tid >> 5;
    int wm = warp & 1, wn = warp >> 1;
    int z     = blockIdx.z;
    int bk    = z >> 1;
    int slice = z & 1;
    int b  = bk >> 1;
    int e  = g_topi[bk];
    int s0 = blockIdx.y * 128, d0 = blockIdx.x * 128;
    int kbase = slice * (FFf / 2);

    const __half* Ah = g_hh + ((size_t)bk * Ss + s0) * FFf + kbase;
    const __half* Al = g_hl + ((size_t)bk * Ss + s0) * FFf + kbase;
    const __half* Bw = g_w2 + ((size_t)e * Dd + d0) * FFf + kbase;

    float d[4][8][4];
#pragma unroll
    for (int mt = 0; mt < 4; mt++)
#pragma unroll
        for (int nt = 0; nt < 8; nt++)
#pragma unroll
            for (int q = 0; q < 4; q++) d[mt][nt][q] = 0.f;

    const int nk = (FFf / 2) / 32;   // 48
    load_stage(sb, Ah, Al, FFf, Bw, FFf, tid);
    CP_COMMIT();

    for (int ks = 0; ks < nk; ks++) {
        uint32_t buf = (ks & 1) ? sb + STAGE : sb;
        if (ks + 1 < nk) {
            int kk = (ks + 1) * 32;
            uint32_t nbuf = ((ks + 1) & 1) ? sb + STAGE : sb;
            load_stage(nbuf, Ah + kk, Al + kk, FFf, Bw + kk, FFf, tid);
            CP_COMMIT();
            CP_WAIT1();
        } else {
            CP_WAIT0();
        }
        __syncthreads();
        compute_stage(buf, wm, wn, lane, d);
        __syncthreads();
    }

    // epilogue: + topv * b2[e] (slice 0 only), write fp32 partial
    float tv = (slice == 0) ? g_topv[bk] : 0.f;
    const float* b2e = b2 + (size_t)e * Dd + d0;
    float* dst = g_mixp + (size_t)((bk & 1) * 2 + slice) * ((size_t)Bb * Ss * Dd);
    int lrow = lane >> 2;
    int lcol = (lane & 3) * 2;
#pragma unroll
    for (int mt = 0; mt < 4; mt++) {
#pragma unroll
        for (int nt = 0; nt < 8; nt++) {
            int nn = wn * 64 + nt * 8 + lcol;
            float bias0 = tv * b2e[nn];
            float bias1 = tv * b2e[nn + 1];
#pragma unroll
            for (int half_i = 0; half_i < 2; half_i++) {
                int s = s0 + wm * 64 + mt * 16 + lrow + half_i * 8;
                float2 o;
                o.x = d[mt][nt][2 * half_i]     + bias0;
                o.y = d[mt][nt][2 * half_i + 1] + bias1;
                *(float2*)(dst + ((size_t)b * Ss + s) * Dd + d0 + nn) = o;
            }
        }
    }
}

// ======================= kernel: out = x + LN(sum of 4 partials) =======================
__global__ void ln_kernel(const float* __restrict__ x,
                          const float* __restrict__ gamma,
                          const float* __restrict__ beta,
                          float* __restrict__ out) {
    int row = blockIdx.x;
    int tid = threadIdx.x;
    const size_t BSD = (size_t)Bb * Ss * Dd;
    const float* m0 = g_mixp + (size_t)row * Dd;
    const float* m1 = m0 + BSD;
    const float* m2 = m1 + BSD;
    const float* m3 = m2 + BSD;

    float v0 = m0[tid]       + m1[tid]       + m2[tid]       + m3[tid];
    float v1 = m0[tid + 256] + m1[tid + 256] + m2[tid + 256] + m3[tid + 256];
    float v2 = m0[tid + 512] + m1[tid + 512] + m2[tid + 512] + m3[tid + 512];
    __shared__ float red[256], red2[256];
    red[tid]  = v0 + v1 + v2;
    red2[tid] = v0 * v0 + v1 * v1 + v2 * v2;
    __syncthreads();
    for (int s = 128; s > 0; s >>= 1) {
        if (tid < s) { red[tid] += red[tid + s]; red2[tid] += red2[tid + s]; }
        __syncthreads();
    }
    __shared__ float smu, sinv;
    if (tid == 0) {
        float mu  = red[0] * (1.0f / Dd);
        float var = red2[0] * (1.0f / Dd) - mu * mu;
        smu = mu; sinv = rsqrtf(var + 1e-5f);
    }
    __syncthreads();
    float mu = smu, inv = sinv;
    const float* xr = x + (size_t)row * Dd;
    float* o = out + (size_t)row * Dd;
    float vv[3] = {v0, v1, v2};
#pragma unroll
    for (int q = 0; q < 3; q++) {
        int dd = tid + q * 256;
        o[dd] = xr[dd] + (vv[q] - mu) * inv * gamma[dd] + beta[dd];
    }
}

// ======================= launch =======================
extern "C" void kernel_launch(void* const* d_in, const int* in_sizes, int n_in,
                              void* d_out, int out_size) {
    const float* x   = (const float*)d_in[0];
    const float* ts  = (const float*)d_in[1];
    const float* W1  = (const float*)d_in[2];
    const float* b1  = (const float*)d_in[3];
    const float* W2  = (const float*)d_in[4];
    const float* b2  = (const float*)d_in[5];
    const float* rw  = (const float*)d_in[6];
    const float* rb  = (const float*)d_in[7];
    const float* gam = (const float*)d_in[8];
    const float* bet = (const float*)d_in[9];

    float* out   = (float*)d_out;
    float* probs = out + (size_t)Bb * Ss * Dd;

    cudaFuncSetAttribute(gemm1_mma, cudaFuncAttributeMaxDynamicSharedMemorySize, SMEM_BYTES);
    cudaFuncSetAttribute(gemm2_mma, cudaFuncAttributeMaxDynamicSharedMemorySize, SMEM_BYTES);

    router_kernel<<<Bb, 256>>>(x, ts, rw, rb, probs);
    split_x_kernel<<<(Bb * Ss * Dd) / 1024, 256>>>(x);
    split_w_kernel<<<dim3(FFf / 32, Dd / 32, Ee), dim3(32, 8)>>>(W1, 0, Dd, FFf);
    split_w_kernel<<<dim3(Dd / 32, FFf / 32, Ee), dim3(32, 8)>>>(W2, 1, FFf, Dd);

    gemm1_mma<<<dim3(FFf / 128, Ss / 128, Bb * KK), 128, SMEM_BYTES>>>(b1);
    gemm2_mma<<<dim3(Dd / 128, Ss / 128, Bb * KK * 2), 128, SMEM_BYTES>>>(b2);

    ln_kernel<<<Bb * Ss, 256>>>(x, gam, bet, out);
}

// round 8
// speedup vs baseline: 4.9197x; 1.2450x over previous
#include <cuda_runtime.h>
#include <cuda_fp16.h>
#include <math.h>
#include <stdint.h>

#define Bb 8
#define Ss 1024
#define Dd 768
#define FFf 3072
#define Ee 8
#define KK 2

// ======================= scratch (no allocs allowed) =======================
__device__ __align__(256) __half g_xh[(size_t)Bb * Ss * Dd];
__device__ __align__(256) __half g_xl[(size_t)Bb * Ss * Dd];
__device__ __align__(256) __half g_w1[(size_t)Ee * FFf * Dd];    // W1^T [E,FF,D] fp16
__device__ __align__(256) __half g_w2[(size_t)Ee * Dd * FFf];    // W2^T [E,D,FF] fp16
__device__ __align__(256) __half g_hh[(size_t)Bb * KK * Ss * FFf]; // topv*gelu(xW1+b1) fp16
__device__ __align__(256) float g_mixp[(size_t)4 * Bb * Ss * Dd];  // 4 partials
__device__ int   g_topi[Bb * KK];
__device__ float g_topv[Bb * KK];

// ======================= PTX helpers (base ISA sm_80-era) =======================
__device__ __forceinline__ uint32_t smem_u32(const void* p) {
    uint32_t a;
    asm("{ .reg .u64 t; cvta.to.shared.u64 t, %1; cvt.u32.u64 %0, t; }"
        : "=r"(a) : "l"(p));
    return a;
}
__device__ __forceinline__ void cp16(uint32_t s, const void* g) {
    asm volatile("cp.async.cg.shared.global [%0], [%1], 16;" :: "r"(s), "l"(g) : "memory");
}
#define CP_COMMIT() asm volatile("cp.async.commit_group;" ::: "memory")
#define CP_WAIT1()  asm volatile("cp.async.wait_group 1;" ::: "memory")
#define CP_WAIT0()  asm volatile("cp.async.wait_group 0;" ::: "memory")

#define LDSM4(r, addr) \
    asm volatile("ldmatrix.sync.aligned.m8n8.x4.shared.b16 {%0,%1,%2,%3}, [%4];" \
        : "=r"((r)[0]), "=r"((r)[1]), "=r"((r)[2]), "=r"((r)[3]) : "r"(addr))

__device__ __forceinline__ void mma16816(float* d, const uint32_t* a, const uint32_t* b) {
    asm volatile(
        "mma.sync.aligned.m16n8k16.row.col.f32.f16.f16.f32 "
        "{%0,%1,%2,%3}, {%4,%5,%6,%7}, {%8,%9}, {%0,%1,%2,%3};"
        : "+f"(d[0]), "+f"(d[1]), "+f"(d[2]), "+f"(d[3])
        : "r"(a[0]), "r"(a[1]), "r"(a[2]), "r"(a[3]), "r"(b[0]), "r"(b[1]));
}

// fast gelu: tanh.approx.f32 (max rel err ~2^-11)
__device__ __forceinline__ float gelu_fast(float v) {
    float u = v * (0.7978845608028654f + 0.035677408136300125f * v * v);
    float t;
    asm("tanh.approx.f32 %0, %1;" : "=f"(t) : "f"(u));
    return 0.5f * v * (1.f + t);
}

// smem tile geometry: 128 rows x 32 fp16, rows padded to 40 halves (80B)
#define ROWB   80
#define ARRB   10240                // 128 * 80
#define STAGE1 30720                // gemm1: 3 arrays (Ah, Al, B)
#define STAGE2 20480                // gemm2: 2 arrays (A, B)
#define SMEM1_BYTES (2 * STAGE1)
#define SMEM2_BYTES (2 * STAGE2)

// gemm1 stage load: A (128x32) hi/lo + B (128x32)
__device__ __forceinline__ void load_stage3(uint32_t sbase,
                                            const __half* Ah, const __half* Al, size_t ldA,
                                            const __half* Bw, size_t ldB,
                                            int tid) {
#pragma unroll
    for (int i = 0; i < 4; i++) {
        int c   = tid + i * 128;          // 0..511
        int row = c >> 2, q = c & 3;
        uint32_t so = (uint32_t)(row * ROWB + q * 16);
        size_t goA = (size_t)row * ldA + q * 8;
        size_t goB = (size_t)row * ldB + q * 8;
        cp16(sbase + so,            Ah + goA);
        cp16(sbase + ARRB + so,     Al + goA);
        cp16(sbase + 2 * ARRB + so, Bw + goB);
    }
}

// gemm2 stage load: A (128x32) + B (128x32)
__device__ __forceinline__ void load_stage2(uint32_t sbase,
                                            const __half* A, size_t ldA,
                                            const __half* Bw, size_t ldB,
                                            int tid) {
#pragma unroll
    for (int i = 0; i < 4; i++) {
        int c   = tid + i * 128;
        int row = c >> 2, q = c & 3;
        uint32_t so = (uint32_t)(row * ROWB + q * 16);
        cp16(sbase + so,        A  + (size_t)row * ldA + q * 8);
        cp16(sbase + ARRB + so, Bw + (size_t)row * ldB + q * 8);
    }
}

// gemm1 compute stage, warp tile 64x64: D += Ah*B + Al*B
__device__ __forceinline__ void compute_stage3(uint32_t sbase, int wm, int wn, int lane,
                                               float d[4][8][4]) {
#pragma unroll
    for (int kb = 0; kb < 2; kb++) {
        uint32_t ah[4][4], al[4][4];
#pragma unroll
        for (int mt = 0; mt < 4; mt++) {
            int row  = wm * 64 + mt * 16 + (lane & 15);
            int kcol = kb * 16 + (lane >> 4) * 8;
            uint32_t ad = sbase + row * ROWB + kcol * 2;
            LDSM4(ah[mt], ad);
            LDSM4(al[mt], ad + ARRB);
        }
        int nbase = wn * 64 + ((lane >> 4) & 1) * 8 + (lane & 7);
        int kcol  = kb * 16 + ((lane >> 3) & 1) * 8;
        uint32_t bbase = sbase + 2 * ARRB + kcol * 2;

        uint32_t bf[2][2][2];
        {
            uint32_t r[4];
            LDSM4(r, bbase + nbase * ROWB);
            bf[0][0][0] = r[0]; bf[0][0][1] = r[1];
            bf[0][1][0] = r[2]; bf[0][1][1] = r[3];
        }
#pragma unroll
        for (int p = 0; p < 4; p++) {
            int cur = p & 1, nxt = cur ^ 1;
            if (p < 3) {
                uint32_t r[4];
                LDSM4(r, bbase + (nbase + (p + 1) * 16) * ROWB);
                bf[nxt][0][0] = r[0]; bf[nxt][0][1] = r[1];
                bf[nxt][1][0] = r[2]; bf[nxt][1][1] = r[3];
            }
#pragma unroll
            for (int g = 0; g < 2; g++) {
                int nt = 2 * p + g;
#pragma unroll
                for (int mt = 0; mt < 4; mt++) {
                    mma16816(d[mt][nt], ah[mt], bf[cur][g]);
                    mma16816(d[mt][nt], al[mt], bf[cur][g]);
                }
            }
        }
    }
}

// gemm2 compute stage, warp tile 64x64: D += A*B  (single MMA path)
__device__ __forceinline__ void compute_stage2(uint32_t sbase, int wm, int wn, int lane,
                                               float d[4][8][4]) {
#pragma unroll
    for (int kb = 0; kb < 2; kb++) {
        uint32_t af[4][4];
#pragma unroll
        for (int mt = 0; mt < 4; mt++) {
            int row  = wm * 64 + mt * 16 + (lane & 15);
            int kcol = kb * 16 + (lane >> 4) * 8;
            LDSM4(af[mt], sbase + row * ROWB + kcol * 2);
        }
        int nbase = wn * 64 + ((lane >> 4) & 1) * 8 + (lane & 7);
        int kcol  = kb * 16 + ((lane >> 3) & 1) * 8;
        uint32_t bbase = sbase + ARRB + kcol * 2;

        uint32_t bf[2][2][2];
        {
            uint32_t r[4];
            LDSM4(r, bbase + nbase * ROWB);
            bf[0][0][0] = r[0]; bf[0][0][1] = r[1];
            bf[0][1][0] = r[2]; bf[0][1][1] = r[3];
        }
#pragma unroll
        for (int p = 0; p < 4; p++) {
            int cur = p & 1, nxt = cur ^ 1;
            if (p < 3) {
                uint32_t r[4];
                LDSM4(r, bbase + (nbase + (p + 1) * 16) * ROWB);
                bf[nxt][0][0] = r[0]; bf[nxt][0][1] = r[1];
                bf[nxt][1][0] = r[2]; bf[nxt][1][1] = r[3];
            }
#pragma unroll
            for (int g = 0; g < 2; g++) {
                int nt = 2 * p + g;
#pragma unroll
                for (int mt = 0; mt < 4; mt++)
                    mma16816(d[mt][nt], af[mt], bf[cur][g]);
            }
        }
    }
}

// ======================= kernel: router =======================
__global__ void router_kernel(const float* __restrict__ x,
                              const float* __restrict__ ts,
                              const float* __restrict__ rw,
                              const float* __restrict__ rb,
                              float* __restrict__ probs_out) {
    int b   = blockIdx.x;
    int tid = threadIdx.x;
    __shared__ float feat[2 * Dd];
    for (int d = tid; d < Dd; d += 256) {
        float acc = 0.f;
        const float* xb = x + (size_t)b * Ss * Dd + d;
        for (int s = 0; s < Ss; s++) acc += xb[(size_t)s * Dd];
        feat[d]      = acc * (1.0f / Ss);
        feat[Dd + d] = ts[b * Dd + d];
    }
    __syncthreads();

    __shared__ float red[256];
    __shared__ float logits[Ee];
    for (int e = 0; e < Ee; e++) {
        float p = 0.f;
        for (int d = tid; d < 2 * Dd; d += 256) p += feat[d] * rw[d * Ee + e];
        red[tid] = p;
        __syncthreads();
        for (int s = 128; s > 0; s >>= 1) {
            if (tid < s) red[tid] += red[tid + s];
            __syncthreads();
        }
        if (tid == 0) logits[e] = red[0] + rb[e];
        __syncthreads();
    }

    if (tid == 0) {
        float mx = logits[0];
        for (int e = 1; e < Ee; e++) mx = fmaxf(mx, logits[e]);
        float p[Ee], den = 0.f;
        for (int e = 0; e < Ee; e++) { p[e] = expf(logits[e] - mx); den += p[e]; }
        float inv = 1.f / den;
        for (int e = 0; e < Ee; e++) { p[e] *= inv; probs_out[b * Ee + e] = p[e]; }
        int i0 = 0;
        for (int e = 1; e < Ee; e++) if (p[e] > p[i0]) i0 = e;
        int i1 = -1;
        for (int e = 0; e < Ee; e++) {
            if (e == i0) continue;
            if (i1 < 0 || p[e] > p[i1]) i1 = e;
        }
        g_topi[b * KK + 0] = i0;  g_topv[b * KK + 0] = p[i0];
        g_topi[b * KK + 1] = i1;  g_topv[b * KK + 1] = p[i1];
    }
}

// ======================= kernel: split x into fp16 hi/lo =======================
__global__ void split_x_kernel(const float* __restrict__ x) {
    size_t i = ((size_t)blockIdx.x * blockDim.x + threadIdx.x) * 4;
    float4 v = *(const float4*)(x + i);
    float vv[4] = {v.x, v.y, v.z, v.w};
    __half h[4], l[4];
#pragma unroll
    for (int j = 0; j < 4; j++) {
        h[j] = __float2half_rn(vv[j]);
        l[j] = __float2half_rn(vv[j] - __half2float(h[j]));
    }
    __half2 h01 = __halves2half2(h[0], h[1]);
    __half2 h23 = __halves2half2(h[2], h[3]);
    __half2 l01 = __halves2half2(l[0], l[1]);
    __half2 l23 = __halves2half2(l[2], l[3]);
    uint2 uh, ul;
    uh.x = *(uint32_t*)&h01; uh.y = *(uint32_t*)&h23;
    ul.x = *(uint32_t*)&l01; ul.y = *(uint32_t*)&l23;
    *(uint2*)(g_xh + i) = uh;
    *(uint2*)(g_xl + i) = ul;
}

// ======================= kernel: transpose W -> fp16 =======================
__global__ void split_w_kernel(const float* __restrict__ W, int which, int R, int C) {
    __shared__ float t[32][33];
    int e  = blockIdx.z;
    int c0 = blockIdx.x * 32, r0 = blockIdx.y * 32;
    const float* Wp = W + (size_t)e * R * C;
#pragma unroll
    for (int i = 0; i < 4; i++) {
        int r = r0 + threadIdx.y + i * 8;
        t[threadIdx.y + i * 8][threadIdx.x] = Wp[(size_t)r * C + c0 + threadIdx.x];
    }
    __syncthreads();
    __half* th = which ? g_w2 : g_w1;
#pragma unroll
    for (int i = 0; i < 4; i++) {
        int c = c0 + threadIdx.y + i * 8;
        float v = t[threadIdx.x][threadIdx.y + i * 8];
        size_t o = ((size_t)e * C + c) * R + r0 + threadIdx.x;
        th[o] = __float2half_rn(v);
    }
}

// ======================= GEMM1: h = topv * gelu(x W1 + b1) =======================
__global__ __launch_bounds__(128, 2) void gemm1_mma(const float* __restrict__ b1) {
    extern __shared__ char smraw[];
    uint32_t sb = smem_u32(smraw);

    int tid = threadIdx.x, lane = tid & 31, warp = tid >> 5;
    int wm = warp & 1, wn = warp >> 1;
    int bk = blockIdx.z;
    int b  = bk >> 1;
    int e  = g_topi[bk];
    int s0 = blockIdx.y * 128, f0 = blockIdx.x * 128;

    const __half* Ah = g_xh + ((size_t)b * Ss + s0) * Dd;
    const __half* Al = g_xl + ((size_t)b * Ss + s0) * Dd;
    const __half* Bw = g_w1 + ((size_t)e * FFf + f0) * Dd;

    float d[4][8][4];
#pragma unroll
    for (int mt = 0; mt < 4; mt++)
#pragma unroll
        for (int nt = 0; nt < 8; nt++)
#pragma unroll
            for (int q = 0; q < 4; q++) d[mt][nt][q] = 0.f;

    const int nk = Dd / 32;    // 24
    load_stage3(sb, Ah, Al, Dd, Bw, Dd, tid);
    CP_COMMIT();

    for (int ks = 0; ks < nk; ks++) {
        uint32_t buf = (ks & 1) ? sb + STAGE1 : sb;
        if (ks + 1 < nk) {
            int kk = (ks + 1) * 32;
            uint32_t nbuf = ((ks + 1) & 1) ? sb + STAGE1 : sb;
            load_stage3(nbuf, Ah + kk, Al + kk, Dd, Bw + kk, Dd, tid);
            CP_COMMIT();
            CP_WAIT1();
        } else {
            CP_WAIT0();
        }
        __syncthreads();
        compute_stage3(buf, wm, wn, lane, d);
        __syncthreads();
    }

    // epilogue: + b1, gelu, * topv, store fp16
    const float* b1e = b1 + (size_t)e * FFf + f0;
    float w = g_topv[bk];
    int lrow = lane >> 2;
    int lcol = (lane & 3) * 2;
#pragma unroll
    for (int mt = 0; mt < 4; mt++) {
#pragma unroll
        for (int nt = 0; nt < 8; nt++) {
            int fc = wn * 64 + nt * 8 + lcol;
            float bb0 = b1e[fc];
            float bb1 = b1e[fc + 1];
#pragma unroll
            for (int half_i = 0; half_i < 2; half_i++) {
                int s = s0 + wm * 64 + mt * 16 + lrow + half_i * 8;
                float g0 = w * gelu_fast(d[mt][nt][2 * half_i]     + bb0);
                float g1 = w * gelu_fast(d[mt][nt][2 * half_i + 1] + bb1);
                __half2 hh = __halves2half2(__float2half_rn(g0), __float2half_rn(g1));
                size_t off = ((size_t)bk * Ss + s) * FFf + f0 + fc;
                *(uint32_t*)(g_hh + off) = *(uint32_t*)&hh;
            }
        }
    }
}

// ======================= GEMM2 (expert- and K-split, single fp16) =======================
// grid (Dd/128, Ss/128, B*K*2); z = bk*2 + slice (slice = half of FF)
__global__ __launch_bounds__(128, 2) void gemm2_mma(const float* __restrict__ b2) {
    extern __shared__ char smraw[];
    uint32_t sb = smem_u32(smraw);

    int tid = threadIdx.x, lane = tid & 31, warp = tid >> 5;
    int wm = warp & 1, wn = warp >> 1;
    int z     = blockIdx.z;
    int bk    = z >> 1;
    int slice = z & 1;
    int b  = bk >> 1;
    int e  = g_topi[bk];
    int s0 = blockIdx.y * 128, d0 = blockIdx.x * 128;
    int kbase = slice * (FFf / 2);

    const __half* A  = g_hh + ((size_t)bk * Ss + s0) * FFf + kbase;
    const __half* Bw = g_w2 + ((size_t)e * Dd + d0) * FFf + kbase;

    float d[4][8][4];
#pragma unroll
    for (int mt = 0; mt < 4; mt++)
#pragma unroll
        for (int nt = 0; nt < 8; nt++)
#pragma unroll
            for (int q = 0; q < 4; q++) d[mt][nt][q] = 0.f;

    const int nk = (FFf / 2) / 32;   // 48
    load_stage2(sb, A, FFf, Bw, FFf, tid);
    CP_COMMIT();

    for (int ks = 0; ks < nk; ks++) {
        uint32_t buf = (ks & 1) ? sb + STAGE2 : sb;
        if (ks + 1 < nk) {
            int kk = (ks + 1) * 32;
            uint32_t nbuf = ((ks + 1) & 1) ? sb + STAGE2 : sb;
            load_stage2(nbuf, A + kk, FFf, Bw + kk, FFf, tid);
            CP_COMMIT();
            CP_WAIT1();
        } else {
            CP_WAIT0();
        }
        __syncthreads();
        compute_stage2(buf, wm, wn, lane, d);
        __syncthreads();
    }

    // epilogue: + topv * b2[e] (slice 0 only), write fp32 partial
    float tv = (slice == 0) ? g_topv[bk] : 0.f;
    const float* b2e = b2 + (size_t)e * Dd + d0;
    float* dst = g_mixp + (size_t)((bk & 1) * 2 + slice) * ((size_t)Bb * Ss * Dd);
    int lrow = lane >> 2;
    int lcol = (lane & 3) * 2;
#pragma unroll
    for (int mt = 0; mt < 4; mt++) {
#pragma unroll
        for (int nt = 0; nt < 8; nt++) {
            int nn = wn * 64 + nt * 8 + lcol;
            float bias0 = tv * b2e[nn];
            float bias1 = tv * b2e[nn + 1];
#pragma unroll
            for (int half_i = 0; half_i < 2; half_i++) {
                int s = s0 + wm * 64 + mt * 16 + lrow + half_i * 8;
                float2 o;
                o.x = d[mt][nt][2 * half_i]     + bias0;
                o.y = d[mt][nt][2 * half_i + 1] + bias1;
                *(float2*)(dst + ((size_t)b * Ss + s) * Dd + d0 + nn) = o;
            }
        }
    }
}

// ======================= kernel: out = x + LN(sum of 4 partials) =======================
__global__ void ln_kernel(const float* __restrict__ x,
                          const float* __restrict__ gamma,
                          const float* __restrict__ beta,
                          float* __restrict__ out) {
    int row = blockIdx.x;
    int tid = threadIdx.x;
    const size_t BSD = (size_t)Bb * Ss * Dd;
    const float* m0 = g_mixp + (size_t)row * Dd;
    const float* m1 = m0 + BSD;
    const float* m2 = m1 + BSD;
    const float* m3 = m2 + BSD;

    float v0 = m0[tid]       + m1[tid]       + m2[tid]       + m3[tid];
    float v1 = m0[tid + 256] + m1[tid + 256] + m2[tid + 256] + m3[tid + 256];
    float v2 = m0[tid + 512] + m1[tid + 512] + m2[tid + 512] + m3[tid + 512];
    __shared__ float red[256], red2[256];
    red[tid]  = v0 + v1 + v2;
    red2[tid] = v0 * v0 + v1 * v1 + v2 * v2;
    __syncthreads();
    for (int s = 128; s > 0; s >>= 1) {
        if (tid < s) { red[tid] += red[tid + s]; red2[tid] += red2[tid + s]; }
        __syncthreads();
    }
    __shared__ float smu, sinv;
    if (tid == 0) {
        float mu  = red[0] * (1.0f / Dd);
        float var = red2[0] * (1.0f / Dd) - mu * mu;
        smu = mu; sinv = rsqrtf(var + 1e-5f);
    }
    __syncthreads();
    float mu = smu, inv = sinv;
    const float* xr = x + (size_t)row * Dd;
    float* o = out + (size_t)row * Dd;
    float vv[3] = {v0, v1, v2};
#pragma unroll
    for (int q = 0; q < 3; q++) {
        int dd = tid + q * 256;
        o[dd] = xr[dd] + (vv[q] - mu) * inv * gamma[dd] + beta[dd];
    }
}

// ======================= launch =======================
extern "C" void kernel_launch(void* const* d_in, const int* in_sizes, int n_in,
                              void* d_out, int out_size) {
    const float* x   = (const float*)d_in[0];
    const float* ts  = (const float*)d_in[1];
    const float* W1  = (const float*)d_in[2];
    const float* b1  = (const float*)d_in[3];
    const float* W2  = (const float*)d_in[4];
    const float* b2  = (const float*)d_in[5];
    const float* rw  = (const float*)d_in[6];
    const float* rb  = (const float*)d_in[7];
    const float* gam = (const float*)d_in[8];
    const float* bet = (const float*)d_in[9];

    float* out   = (float*)d_out;
    float* probs = out + (size_t)Bb * Ss * Dd;

    cudaFuncSetAttribute(gemm1_mma, cudaFuncAttributeMaxDynamicSharedMemorySize, SMEM1_BYTES);
    cudaFuncSetAttribute(gemm2_mma, cudaFuncAttributeMaxDynamicSharedMemorySize, SMEM2_BYTES);

    router_kernel<<<Bb, 256>>>(x, ts, rw, rb, probs);
    split_x_kernel<<<(Bb * Ss * Dd) / 1024, 256>>>(x);
    split_w_kernel<<<dim3(FFf / 32, Dd / 32, Ee), dim3(32, 8)>>>(W1, 0, Dd, FFf);
    split_w_kernel<<<dim3(Dd / 32, FFf / 32, Ee), dim3(32, 8)>>>(W2, 1, FFf, Dd);

    gemm1_mma<<<dim3(FFf / 128, Ss / 128, Bb * KK), 128, SMEM1_BYTES>>>(b1);
    gemm2_mma<<<dim3(Dd / 128, Ss / 128, Bb * KK * 2), 128, SMEM2_BYTES>>>(b2);

    ln_kernel<<<Bb * Ss, 256>>>(x, gam, bet, out);
}

// round 9
// speedup vs baseline: 4.9293x; 1.0019x over previous
#include <cuda_runtime.h>
#include <cuda_fp16.h>
#include <math.h>
#include <stdint.h>

#define Bb 8
#define Ss 1024
#define Dd 768
#define FFf 3072
#define Ee 8
#define KK 2

// ======================= scratch (no allocs allowed) =======================
__device__ __align__(256) __half g_xh[(size_t)Bb * Ss * Dd];
__device__ __align__(256) __half g_xl[(size_t)Bb * Ss * Dd];
__device__ __align__(256) __half g_w1[(size_t)Ee * FFf * Dd];    // W1^T [E,FF,D] fp16
__device__ __align__(256) __half g_w2[(size_t)Ee * Dd * FFf];    // W2^T [E,D,FF] fp16
__device__ __align__(256) __half g_hh[(size_t)Bb * KK * Ss * FFf]; // topv*gelu(xW1+b1) fp16
__device__ __align__(256) float g_mixp[(size_t)4 * Bb * Ss * Dd];  // 4 partials
__device__ int   g_topi[Bb * KK];
__device__ float g_topv[Bb * KK];

// ======================= PTX helpers (base ISA sm_80-era) =======================
__device__ __forceinline__ uint32_t smem_u32(const void* p) {
    uint32_t a;
    asm("{ .reg .u64 t; cvta.to.shared.u64 t, %1; cvt.u32.u64 %0, t; }"
        : "=r"(a) : "l"(p));
    return a;
}
__device__ __forceinline__ void cp16(uint32_t s, const void* g) {
    asm volatile("cp.async.cg.shared.global [%0], [%1], 16;" :: "r"(s), "l"(g) : "memory");
}
#define CP_COMMIT() asm volatile("cp.async.commit_group;" ::: "memory")
#define CP_WAIT1()  asm volatile("cp.async.wait_group 1;" ::: "memory")
#define CP_WAIT0()  asm volatile("cp.async.wait_group 0;" ::: "memory")

#define LDSM4(r, addr) \
    asm volatile("ldmatrix.sync.aligned.m8n8.x4.shared.b16 {%0,%1,%2,%3}, [%4];" \
        : "=r"((r)[0]), "=r"((r)[1]), "=r"((r)[2]), "=r"((r)[3]) : "r"(addr))

__device__ __forceinline__ void mma16816(float* d, const uint32_t* a, const uint32_t* b) {
    asm volatile(
        "mma.sync.aligned.m16n8k16.row.col.f32.f16.f16.f32 "
        "{%0,%1,%2,%3}, {%4,%5,%6,%7}, {%8,%9}, {%0,%1,%2,%3};"
        : "+f"(d[0]), "+f"(d[1]), "+f"(d[2]), "+f"(d[3])
        : "r"(a[0]), "r"(a[1]), "r"(a[2]), "r"(a[3]), "r"(b[0]), "r"(b[1]));
}

// fast gelu: tanh.approx.f32 (max rel err ~2^-11)
__device__ __forceinline__ float gelu_fast(float v) {
    float u = v * (0.7978845608028654f + 0.035677408136300125f * v * v);
    float t;
    asm("tanh.approx.f32 %0, %1;" : "=f"(t) : "f"(u));
    return 0.5f * v * (1.f + t);
}

// smem tile geometry: 128 rows x 32 fp16, rows padded to 40 halves (80B)
#define ROWB   80
#define ARRB   10240                // 128 * 80
#define STAGE1 30720                // gemm1: 3 arrays (Ah, Al, B)
#define STAGE2 20480                // gemm2: 2 arrays (A, B)
#define SMEM1_BYTES (2 * STAGE1)
#define SMEM2_BYTES (2 * STAGE2)

// gemm1 stage load: A (128x32) hi/lo + B (128x32)
__device__ __forceinline__ void load_stage3(uint32_t sbase,
                                            const __half* Ah, const __half* Al, size_t ldA,
                                            const __half* Bw, size_t ldB,
                                            int tid) {
#pragma unroll
    for (int i = 0; i < 4; i++) {
        int c   = tid + i * 128;          // 0..511
        int row = c >> 2, q = c & 3;
        uint32_t so = (uint32_t)(row * ROWB + q * 16);
        size_t goA = (size_t)row * ldA + q * 8;
        size_t goB = (size_t)row * ldB + q * 8;
        cp16(sbase + so,            Ah + goA);
        cp16(sbase + ARRB + so,     Al + goA);
        cp16(sbase + 2 * ARRB + so, Bw + goB);
    }
}

// gemm2 stage load: A (128x32) + B (128x32)
__device__ __forceinline__ void load_stage2(uint32_t sbase,
                                            const __half* A, size_t ldA,
                                            const __half* Bw, size_t ldB,
                                            int tid) {
#pragma unroll
    for (int i = 0; i < 4; i++) {
        int c   = tid + i * 128;
        int row = c >> 2, q = c & 3;
        uint32_t so = (uint32_t)(row * ROWB + q * 16);
        cp16(sbase + so,        A  + (size_t)row * ldA + q * 8);
        cp16(sbase + ARRB + so, Bw + (size_t)row * ldB + q * 8);
    }
}

// gemm1 compute stage, warp tile 64x64: D += Ah*B + Al*B
__device__ __forceinline__ void compute_stage3(uint32_t sbase, int wm, int wn, int lane,
                                               float d[4][8][4]) {
#pragma unroll
    for (int kb = 0; kb < 2; kb++) {
        uint32_t ah[4][4], al[4][4];
#pragma unroll
        for (int mt = 0; mt < 4; mt++) {
            int row  = wm * 64 + mt * 16 + (lane & 15);
            int kcol = kb * 16 + (lane >> 4) * 8;
            uint32_t ad = sbase + row * ROWB + kcol * 2;
            LDSM4(ah[mt], ad);
            LDSM4(al[mt], ad + ARRB);
        }
        int nbase = wn * 64 + ((lane >> 4) & 1) * 8 + (lane & 7);
        int kcol  = kb * 16 + ((lane >> 3) & 1) * 8;
        uint32_t bbase = sbase + 2 * ARRB + kcol * 2;

        uint32_t bf[2][2][2];
        {
            uint32_t r[4];
            LDSM4(r, bbase + nbase * ROWB);
            bf[0][0][0] = r[0]; bf[0][0][1] = r[1];
            bf[0][1][0] = r[2]; bf[0][1][1] = r[3];
        }
#pragma unroll
        for (int p = 0; p < 4; p++) {
            int cur = p & 1, nxt = cur ^ 1;
            if (p < 3) {
                uint32_t r[4];
                LDSM4(r, bbase + (nbase + (p + 1) * 16) * ROWB);
                bf[nxt][0][0] = r[0]; bf[nxt][0][1] = r[1];
                bf[nxt][1][0] = r[2]; bf[nxt][1][1] = r[3];
            }
#pragma unroll
            for (int g = 0; g < 2; g++) {
                int nt = 2 * p + g;
#pragma unroll
                for (int mt = 0; mt < 4; mt++) {
                    mma16816(d[mt][nt], ah[mt], bf[cur][g]);
                    mma16816(d[mt][nt], al[mt], bf[cur][g]);
                }
            }
        }
    }
}

// gemm2 compute stage, warp tile 64x64: D += A*B  (single MMA path)
__device__ __forceinline__ void compute_stage2(uint32_t sbase, int wm, int wn, int lane,
                                               float d[4][8][4]) {
#pragma unroll
    for (int kb = 0; kb < 2; kb++) {
        uint32_t af[4][4];
#pragma unroll
        for (int mt = 0; mt < 4; mt++) {
            int row  = wm * 64 + mt * 16 + (lane & 15);
            int kcol = kb * 16 + (lane >> 4) * 8;
            LDSM4(af[mt], sbase + row * ROWB + kcol * 2);
        }
        int nbase = wn * 64 + ((lane >> 4) & 1) * 8 + (lane & 7);
        int kcol  = kb * 16 + ((lane >> 3) & 1) * 8;
        uint32_t bbase = sbase + ARRB + kcol * 2;

        uint32_t bf[2][2][2];
        {
            uint32_t r[4];
            LDSM4(r, bbase + nbase * ROWB);
            bf[0][0][0] = r[0]; bf[0][0][1] = r[1];
            bf[0][1][0] = r[2]; bf[0][1][1] = r[3];
        }
#pragma unroll
        for (int p = 0; p < 4; p++) {
            int cur = p & 1, nxt = cur ^ 1;
            if (p < 3) {
                uint32_t r[4];
                LDSM4(r, bbase + (nbase + (p + 1) * 16) * ROWB);
                bf[nxt][0][0] = r[0]; bf[nxt][0][1] = r[1];
                bf[nxt][1][0] = r[2]; bf[nxt][1][1] = r[3];
            }
#pragma unroll
            for (int g = 0; g < 2; g++) {
                int nt = 2 * p + g;
#pragma unroll
                for (int mt = 0; mt < 4; mt++)
                    mma16816(d[mt][nt], af[mt], bf[cur][g]);
            }
        }
    }
}

// ======================= kernel: router =======================
__global__ void router_kernel(const float* __restrict__ x,
                              const float* __restrict__ ts,
                              const float* __restrict__ rw,
                              const float* __restrict__ rb,
                              float* __restrict__ probs_out) {
    int b   = blockIdx.x;
    int tid = threadIdx.x;
    __shared__ float feat[2 * Dd];
    for (int d = tid; d < Dd; d += 256) {
        float acc = 0.f;
        const float* xb = x + (size_t)b * Ss * Dd + d;
        for (int s = 0; s < Ss; s++) acc += xb[(size_t)s * Dd];
        feat[d]      = acc * (1.0f / Ss);
        feat[Dd + d] = ts[b * Dd + d];
    }
    __syncthreads();

    __shared__ float red[256];
    __shared__ float logits[Ee];
    for (int e = 0; e < Ee; e++) {
        float p = 0.f;
        for (int d = tid; d < 2 * Dd; d += 256) p += feat[d] * rw[d * Ee + e];
        red[tid] = p;
        __syncthreads();
        for (int s = 128; s > 0; s >>= 1) {
            if (tid < s) red[tid] += red[tid + s];
            __syncthreads();
        }
        if (tid == 0) logits[e] = red[0] + rb[e];
        __syncthreads();
    }

    if (tid == 0) {
        float mx = logits[0];
        for (int e = 1; e < Ee; e++) mx = fmaxf(mx, logits[e]);
        float p[Ee], den = 0.f;
        for (int e = 0; e < Ee; e++) { p[e] = expf(logits[e] - mx); den += p[e]; }
        float inv = 1.f / den;
        for (int e = 0; e < Ee; e++) { p[e] *= inv; probs_out[b * Ee + e] = p[e]; }
        int i0 = 0;
        for (int e = 1; e < Ee; e++) if (p[e] > p[i0]) i0 = e;
        int i1 = -1;
        for (int e = 0; e < Ee; e++) {
            if (e == i0) continue;
            if (i1 < 0 || p[e] > p[i1]) i1 = e;
        }
        g_topi[b * KK + 0] = i0;  g_topv[b * KK + 0] = p[i0];
        g_topi[b * KK + 1] = i1;  g_topv[b * KK + 1] = p[i1];
    }
}

// ======================= kernel: split x into fp16 hi/lo =======================
__global__ void split_x_kernel(const float* __restrict__ x) {
    size_t i = ((size_t)blockIdx.x * blockDim.x + threadIdx.x) * 4;
    float4 v = *(const float4*)(x + i);
    float vv[4] = {v.x, v.y, v.z, v.w};
    __half h[4], l[4];
#pragma unroll
    for (int j = 0; j < 4; j++) {
        h[j] = __float2half_rn(vv[j]);
        l[j] = __float2half_rn(vv[j] - __half2float(h[j]));
    }
    __half2 h01 = __halves2half2(h[0], h[1]);
    __half2 h23 = __halves2half2(h[2], h[3]);
    __half2 l01 = __halves2half2(l[0], l[1]);
    __half2 l23 = __halves2half2(l[2], l[3]);
    uint2 uh, ul;
    uh.x = *(uint32_t*)&h01; uh.y = *(uint32_t*)&h23;
    ul.x = *(uint32_t*)&l01; ul.y = *(uint32_t*)&l23;
    *(uint2*)(g_xh + i) = uh;
    *(uint2*)(g_xl + i) = ul;
}

// ======================= kernel: transpose W -> fp16 =======================
__global__ void split_w_kernel(const float* __restrict__ W, int which, int R, int C) {
    __shared__ float t[32][33];
    int e  = blockIdx.z;
    int c0 = blockIdx.x * 32, r0 = blockIdx.y * 32;
    const float* Wp = W + (size_t)e * R * C;
#pragma unroll
    for (int i = 0; i < 4; i++) {
        int r = r0 + threadIdx.y + i * 8;
        t[threadIdx.y + i * 8][threadIdx.x] = Wp[(size_t)r * C + c0 + threadIdx.x];
    }
    __syncthreads();
    __half* th = which ? g_w2 : g_w1;
#pragma unroll
    for (int i = 0; i < 4; i++) {
        int c = c0 + threadIdx.y + i * 8;
        float v = t[threadIdx.x][threadIdx.y + i * 8];
        size_t o = ((size_t)e * C + c) * R + r0 + threadIdx.x;
        th[o] = __float2half_rn(v);
    }
}

// ======================= GEMM1: h = topv * gelu(x W1 + b1) =======================
__global__ __launch_bounds__(128, 2) void gemm1_mma(const float* __restrict__ b1) {
    extern __shared__ char smraw[];
    uint32_t sb = smem_u32(smraw);

    int tid = threadIdx.x, lane = tid & 31, warp = tid >> 5;
    int wm = warp & 1, wn = warp >> 1;
    int bk = blockIdx.z;
    int b  = bk >> 1;
    int e  = g_topi[bk];
    int s0 = blockIdx.y * 128, f0 = blockIdx.x * 128;

    const __half* Ah = g_xh + ((size_t)b * Ss + s0) * Dd;
    const __half* Al = g_xl + ((size_t)b * Ss + s0) * Dd;
    const __half* Bw = g_w1 + ((size_t)e * FFf + f0) * Dd;

    float d[4][8][4];
#pragma unroll
    for (int mt = 0; mt < 4; mt++)
#pragma unroll
        for (int nt = 0; nt < 8; nt++)
#pragma unroll
            for (int q = 0; q < 4; q++) d[mt][nt][q] = 0.f;

    const int nk = Dd / 32;    // 24
    load_stage3(sb, Ah, Al, Dd, Bw, Dd, tid);
    CP_COMMIT();

    for (int ks = 0; ks < nk; ks++) {
        uint32_t buf = (ks & 1) ? sb + STAGE1 : sb;
        if (ks + 1 < nk) {
            int kk = (ks + 1) * 32;
            uint32_t nbuf = ((ks + 1) & 1) ? sb + STAGE1 : sb;
            load_stage3(nbuf, Ah + kk, Al + kk, Dd, Bw + kk, Dd, tid);
            CP_COMMIT();
            CP_WAIT1();
        } else {
            CP_WAIT0();
        }
        __syncthreads();
        compute_stage3(buf, wm, wn, lane, d);
        __syncthreads();
    }

    // epilogue: + b1, gelu, * topv, store fp16
    const float* b1e = b1 + (size_t)e * FFf + f0;
    float w = g_topv[bk];
    int lrow = lane >> 2;
    int lcol = (lane & 3) * 2;
#pragma unroll
    for (int mt = 0; mt < 4; mt++) {
#pragma unroll
        for (int nt = 0; nt < 8; nt++) {
            int fc = wn * 64 + nt * 8 + lcol;
            float bb0 = b1e[fc];
            float bb1 = b1e[fc + 1];
#pragma unroll
            for (int half_i = 0; half_i < 2; half_i++) {
                int s = s0 + wm * 64 + mt * 16 + lrow + half_i * 8;
                float g0 = w * gelu_fast(d[mt][nt][2 * half_i]     + bb0);
                float g1 = w * gelu_fast(d[mt][nt][2 * half_i + 1] + bb1);
                __half2 hh = __halves2half2(__float2half_rn(g0), __float2half_rn(g1));
                size_t off = ((size_t)bk * Ss + s) * FFf + f0 + fc;
                *(uint32_t*)(g_hh + off) = *(uint32_t*)&hh;
            }
        }
    }
}

// ======================= GEMM2 (expert- and K-split, single fp16) =======================
// grid (Dd/128, Ss/128, B*K*2); z = bk*2 + slice (slice = half of FF)
__global__ __launch_bounds__(128, 2) void gemm2_mma(const float* __restrict__ b2) {
    extern __shared__ char smraw[];
    uint32_t sb = smem_u32(smraw);

    int tid = threadIdx.x, lane = tid & 31, warp = tid >> 5;
    int wm = warp & 1, wn = warp >> 1;
    int z     = blockIdx.z;
    int bk    = z >> 1;
    int slice = z & 1;
    int b  = bk >> 1;
    int e  = g_topi[bk];
    int s0 = blockIdx.y * 128, d0 = blockIdx.x * 128;
    int kbase = slice * (FFf / 2);

    const __half* A  = g_hh + ((size_t)bk * Ss + s0) * FFf + kbase;
    const __half* Bw = g_w2 + ((size_t)e * Dd + d0) * FFf + kbase;

    float d[4][8][4];
#pragma unroll
    for (int mt = 0; mt < 4; mt++)
#pragma unroll
        for (int nt = 0; nt < 8; nt++)
#pragma unroll
            for (int q = 0; q < 4; q++) d[mt][nt][q] = 0.f;

    const int nk = (FFf / 2) / 32;   // 48
    load_stage2(sb, A, FFf, Bw, FFf, tid);
    CP_COMMIT();

    for (int ks = 0; ks < nk; ks++) {
        uint32_t buf = (ks & 1) ? sb + STAGE2 : sb;
        if (ks + 1 < nk) {
            int kk = (ks + 1) * 32;
            uint32_t nbuf = ((ks + 1) & 1) ? sb + STAGE2 : sb;
            load_stage2(nbuf, A + kk, FFf, Bw + kk, FFf, tid);
            CP_COMMIT();
            CP_WAIT1();
        } else {
            CP_WAIT0();
        }
        __syncthreads();
        compute_stage2(buf, wm, wn, lane, d);
        __syncthreads();
    }

    // epilogue: + topv * b2[e] (slice 0 only), write fp32 partial
    float tv = (slice == 0) ? g_topv[bk] : 0.f;
    const float* b2e = b2 + (size_t)e * Dd + d0;
    float* dst = g_mixp + (size_t)((bk & 1) * 2 + slice) * ((size_t)Bb * Ss * Dd);
    int lrow = lane >> 2;
    int lcol = (lane & 3) * 2;
#pragma unroll
    for (int mt = 0; mt < 4; mt++) {
#pragma unroll
        for (int nt = 0; nt < 8; nt++) {
            int nn = wn * 64 + nt * 8 + lcol;
            float bias0 = tv * b2e[nn];
            float bias1 = tv * b2e[nn + 1];
#pragma unroll
            for (int half_i = 0; half_i < 2; half_i++) {
                int s = s0 + wm * 64 + mt * 16 + lrow + half_i * 8;
                float2 o;
                o.x = d[mt][nt][2 * half_i]     + bias0;
                o.y = d[mt][nt][2 * half_i + 1] + bias1;
                *(float2*)(dst + ((size_t)b * Ss + s) * Dd + d0 + nn) = o;
            }
        }
    }
}

// ======================= kernel: out = x + LN(sum of 4 partials) =======================
__global__ void ln_kernel(const float* __restrict__ x,
                          const float* __restrict__ gamma,
                          const float* __restrict__ beta,
                          float* __restrict__ out) {
    int row = blockIdx.x;
    int tid = threadIdx.x;
    const size_t BSD = (size_t)Bb * Ss * Dd;
    const float* m0 = g_mixp + (size_t)row * Dd;
    const float* m1 = m0 + BSD;
    const float* m2 = m1 + BSD;
    const float* m3 = m2 + BSD;

    float v0 = m0[tid]       + m1[tid]       + m2[tid]       + m3[tid];
    float v1 = m0[tid + 256] + m1[tid + 256] + m2[tid + 256] + m3[tid + 256];
    float v2 = m0[tid + 512] + m1[tid + 512] + m2[tid + 512] + m3[tid + 512];
    __shared__ float red[256], red2[256];
    red[tid]  = v0 + v1 + v2;
    red2[tid] = v0 * v0 + v1 * v1 + v2 * v2;
    __syncthreads();
    for (int s = 128; s > 0; s >>= 1) {
        if (tid < s) { red[tid] += red[tid + s]; red2[tid] += red2[tid + s]; }
        __syncthreads();
    }
    __shared__ float smu, sinv;
    if (tid == 0) {
        float mu  = red[0] * (1.0f / Dd);
        float var = red2[0] * (1.0f / Dd) - mu * mu;
        smu = mu; sinv = rsqrtf(var + 1e-5f);
    }
    __syncthreads();
    float mu = smu, inv = sinv;
    const float* xr = x + (size_t)row * Dd;
    float* o = out + (size_t)row * Dd;
    float vv[3] = {v0, v1, v2};
#pragma unroll
    for (int q = 0; q < 3; q++) {
        int dd = tid + q * 256;
        o[dd] = xr[dd] + (vv[q] - mu) * inv * gamma[dd] + beta[dd];
    }
}

// ======================= launch =======================
extern "C" void kernel_launch(void* const* d_in, const int* in_sizes, int n_in,
                              void* d_out, int out_size) {
    const float* x   = (const float*)d_in[0];
    const float* ts  = (const float*)d_in[1];
    const float* W1  = (const float*)d_in[2];
    const float* b1  = (const float*)d_in[3];
    const float* W2  = (const float*)d_in[4];
    const float* b2  = (const float*)d_in[5];
    const float* rw  = (const float*)d_in[6];
    const float* rb  = (const float*)d_in[7];
    const float* gam = (const float*)d_in[8];
    const float* bet = (const float*)d_in[9];

    float* out   = (float*)d_out;
    float* probs = out + (size_t)Bb * Ss * Dd;

    cudaFuncSetAttribute(gemm1_mma, cudaFuncAttributeMaxDynamicSharedMemorySize, SMEM1_BYTES);
    cudaFuncSetAttribute(gemm2_mma, cudaFuncAttributeMaxDynamicSharedMemorySize, SMEM2_BYTES);

    router_kernel<<<Bb, 256>>>(x, ts, rw, rb, probs);
    split_x_kernel<<<(Bb * Ss * Dd) / 1024, 256>>>(x);
    split_w_kernel<<<dim3(FFf / 32, Dd / 32, Ee), dim3(32, 8)>>>(W1, 0, Dd, FFf);
    split_w_kernel<<<dim3(Dd / 32, FFf / 32, Ee), dim3(32, 8)>>>(W2, 1, FFf, Dd);

    gemm1_mma<<<dim3(FFf / 128, Ss / 128, Bb * KK), 128, SMEM1_BYTES>>>(b1);
    gemm2_mma<<<dim3(Dd / 128, Ss / 128, Bb * KK * 2), 128, SMEM2_BYTES>>>(b2);

    ln_kernel<<<Bb * Ss, 256>>>(x, gam, bet, out);
}

// round 10
// speedup vs baseline: 6.3062x; 1.2793x over previous
#include <cuda_runtime.h>
#include <cuda_fp16.h>
#include <math.h>
#include <stdint.h>

#define Bb 8
#define Ss 1024
#define Dd 768
#define FFf 3072
#define Ee 8
#define KK 2

// ======================= scratch (no allocs allowed) =======================
__device__ __align__(256) __half g_xh[(size_t)Bb * Ss * Dd];       // x fp16
__device__ __align__(256) __half g_w1[(size_t)Ee * FFf * Dd];      // W1^T [E,FF,D] fp16
__device__ __align__(256) __half g_w2[(size_t)Ee * Dd * FFf];      // W2^T [E,D,FF] fp16
__device__ __align__(256) __half g_hh[(size_t)Bb * KK * Ss * FFf]; // topv*gelu(xW1+b1) fp16
__device__ __align__(256) float g_mixp[(size_t)4 * Bb * Ss * Dd];  // 4 partials
__device__ int   g_topi[Bb * KK];
__device__ float g_topv[Bb * KK];

// ======================= PTX helpers (base ISA sm_80-era) =======================
__device__ __forceinline__ uint32_t smem_u32(const void* p) {
    uint32_t a;
    asm("{ .reg .u64 t; cvta.to.shared.u64 t, %1; cvt.u32.u64 %0, t; }"
        : "=r"(a) : "l"(p));
    return a;
}
__device__ __forceinline__ void cp16(uint32_t s, const void* g) {
    asm volatile("cp.async.cg.shared.global [%0], [%1], 16;" :: "r"(s), "l"(g) : "memory");
}
#define CP_COMMIT() asm volatile("cp.async.commit_group;" ::: "memory")
#define CP_WAIT1()  asm volatile("cp.async.wait_group 1;" ::: "memory")
#define CP_WAIT0()  asm volatile("cp.async.wait_group 0;" ::: "memory")

#define LDSM4(r, addr) \
    asm volatile("ldmatrix.sync.aligned.m8n8.x4.shared.b16 {%0,%1,%2,%3}, [%4];" \
        : "=r"((r)[0]), "=r"((r)[1]), "=r"((r)[2]), "=r"((r)[3]) : "r"(addr))

__device__ __forceinline__ void mma16816(float* d, const uint32_t* a, const uint32_t* b) {
    asm volatile(
        "mma.sync.aligned.m16n8k16.row.col.f32.f16.f16.f32 "
        "{%0,%1,%2,%3}, {%4,%5,%6,%7}, {%8,%9}, {%0,%1,%2,%3};"
        : "+f"(d[0]), "+f"(d[1]), "+f"(d[2]), "+f"(d[3])
        : "r"(a[0]), "r"(a[1]), "r"(a[2]), "r"(a[3]), "r"(b[0]), "r"(b[1]));
}

// fast gelu: tanh.approx.f32 (max rel err ~2^-11)
__device__ __forceinline__ float gelu_fast(float v) {
    float u = v * (0.7978845608028654f + 0.035677408136300125f * v * v);
    float t;
    asm("tanh.approx.f32 %0, %1;" : "=f"(t) : "f"(u));
    return 0.5f * v * (1.f + t);
}

// smem tile geometry: 128 rows x 32 fp16, rows padded to 40 halves (80B)
#define ROWB   80
#define ARRB   10240                // 128 * 80
#define STAGE  20480                // 2 arrays (A, B)
#define SMEM_BYTES (2 * STAGE)

// stage load: A (128x32) + B (128x32)
__device__ __forceinline__ void load_stage(uint32_t sbase,
                                           const __half* A, size_t ldA,
                                           const __half* Bw, size_t ldB,
                                           int tid) {
#pragma unroll
    for (int i = 0; i < 4; i++) {
        int c   = tid + i * 128;
        int row = c >> 2, q = c & 3;
        uint32_t so = (uint32_t)(row * ROWB + q * 16);
        cp16(sbase + so,        A  + (size_t)row * ldA + q * 8);
        cp16(sbase + ARRB + so, Bw + (size_t)row * ldB + q * 8);
    }
}

// compute one K=32 stage, warp tile 64x64: D += A*B (single fp16 MMA path)
__device__ __forceinline__ void compute_stage(uint32_t sbase, int wm, int wn, int lane,
                                              float d[4][8][4]) {
#pragma unroll
    for (int kb = 0; kb < 2; kb++) {
        uint32_t af[4][4];
#pragma unroll
        for (int mt = 0; mt < 4; mt++) {
            int row  = wm * 64 + mt * 16 + (lane & 15);
            int kcol = kb * 16 + (lane >> 4) * 8;
            LDSM4(af[mt], sbase + row * ROWB + kcol * 2);
        }
        int nbase = wn * 64 + ((lane >> 4) & 1) * 8 + (lane & 7);
        int kcol  = kb * 16 + ((lane >> 3) & 1) * 8;
        uint32_t bbase = sbase + ARRB + kcol * 2;

        uint32_t bf[2][2][2];
        {
            uint32_t r[4];
            LDSM4(r, bbase + nbase * ROWB);
            bf[0][0][0] = r[0]; bf[0][0][1] = r[1];
            bf[0][1][0] = r[2]; bf[0][1][1] = r[3];
        }
#pragma unroll
        for (int p = 0; p < 4; p++) {
            int cur = p & 1, nxt = cur ^ 1;
            if (p < 3) {
                uint32_t r[4];
                LDSM4(r, bbase + (nbase + (p + 1) * 16) * ROWB);
                bf[nxt][0][0] = r[0]; bf[nxt][0][1] = r[1];
                bf[nxt][1][0] = r[2]; bf[nxt][1][1] = r[3];
            }
#pragma unroll
            for (int g = 0; g < 2; g++) {
                int nt = 2 * p + g;
#pragma unroll
                for (int mt = 0; mt < 4; mt++)
                    mma16816(d[mt][nt], af[mt], bf[cur][g]);
            }
        }
    }
}

// ======================= kernel: router =======================
__global__ void router_kernel(const float* __restrict__ x,
                              const float* __restrict__ ts,
                              const float* __restrict__ rw,
                              const float* __restrict__ rb,
                              float* __restrict__ probs_out) {
    int b   = blockIdx.x;
    int tid = threadIdx.x;
    __shared__ float feat[2 * Dd];
    for (int d = tid; d < Dd; d += 256) {
        float acc = 0.f;
        const float* xb = x + (size_t)b * Ss * Dd + d;
        for (int s = 0; s < Ss; s++) acc += xb[(size_t)s * Dd];
        feat[d]      = acc * (1.0f / Ss);
        feat[Dd + d] = ts[b * Dd + d];
    }
    __syncthreads();

    __shared__ float red[256];
    __shared__ float logits[Ee];
    for (int e = 0; e < Ee; e++) {
        float p = 0.f;
        for (int d = tid; d < 2 * Dd; d += 256) p += feat[d] * rw[d * Ee + e];
        red[tid] = p;
        __syncthreads();
        for (int s = 128; s > 0; s >>= 1) {
            if (tid < s) red[tid] += red[tid + s];
            __syncthreads();
        }
        if (tid == 0) logits[e] = red[0] + rb[e];
        __syncthreads();
    }

    if (tid == 0) {
        float mx = logits[0];
        for (int e = 1; e < Ee; e++) mx = fmaxf(mx, logits[e]);
        float p[Ee], den = 0.f;
        for (int e = 0; e < Ee; e++) { p[e] = expf(logits[e] - mx); den += p[e]; }
        float inv = 1.f / den;
        for (int e = 0; e < Ee; e++) { p[e] *= inv; probs_out[b * Ee + e] = p[e]; }
        int i0 = 0;
        for (int e = 1; e < Ee; e++) if (p[e] > p[i0]) i0 = e;
        int i1 = -1;
        for (int e = 0; e < Ee; e++) {
            if (e == i0) continue;
            if (i1 < 0 || p[e] > p[i1]) i1 = e;
        }
        g_topi[b * KK + 0] = i0;  g_topv[b * KK + 0] = p[i0];
        g_topi[b * KK + 1] = i1;  g_topv[b * KK + 1] = p[i1];
    }
}

// ======================= kernel: convert x -> fp16 =======================
__global__ void split_x_kernel(const float* __restrict__ x) {
    size_t i = ((size_t)blockIdx.x * blockDim.x + threadIdx.x) * 4;
    float4 v = *(const float4*)(x + i);
    __half2 h01 = __halves2half2(__float2half_rn(v.x), __float2half_rn(v.y));
    __half2 h23 = __halves2half2(__float2half_rn(v.z), __float2half_rn(v.w));
    uint2 uh;
    uh.x = *(uint32_t*)&h01; uh.y = *(uint32_t*)&h23;
    *(uint2*)(g_xh + i) = uh;
}

// ======================= kernel: transpose W -> fp16 =======================
__global__ void split_w_kernel(const float* __restrict__ W, int which, int R, int C) {
    __shared__ float t[32][33];
    int e  = blockIdx.z;
    int c0 = blockIdx.x * 32, r0 = blockIdx.y * 32;
    const float* Wp = W + (size_t)e * R * C;
#pragma unroll
    for (int i = 0; i < 4; i++) {
        int r = r0 + threadIdx.y + i * 8;
        t[threadIdx.y + i * 8][threadIdx.x] = Wp[(size_t)r * C + c0 + threadIdx.x];
    }
    __syncthreads();
    __half* th = which ? g_w2 : g_w1;
#pragma unroll
    for (int i = 0; i < 4; i++) {
        int c = c0 + threadIdx.y + i * 8;
        float v = t[threadIdx.x][threadIdx.y + i * 8];
        size_t o = ((size_t)e * C + c) * R + r0 + threadIdx.x;
        th[o] = __float2half_rn(v);
    }
}

// ======================= GEMM1: h = topv * gelu(x W1 + b1) =======================
// grid (FFf/128, Ss/128, B*K), 128 threads, CTA tile 128x128, warp tile 64x64
__global__ __launch_bounds__(128, 2) void gemm1_mma(const float* __restrict__ b1) {
    extern __shared__ char smraw[];
    uint32_t sb = smem_u32(smraw);

    int tid = threadIdx.x, lane = tid & 31, warp = tid >> 5;
    int wm = warp & 1, wn = warp >> 1;
    int bk = blockIdx.z;
    int b  = bk >> 1;
    int e  = g_topi[bk];
    int s0 = blockIdx.y * 128, f0 = blockIdx.x * 128;

    const __half* A  = g_xh + ((size_t)b * Ss + s0) * Dd;
    const __half* Bw = g_w1 + ((size_t)e * FFf + f0) * Dd;

    float d[4][8][4];
#pragma unroll
    for (int mt = 0; mt < 4; mt++)
#pragma unroll
        for (int nt = 0; nt < 8; nt++)
#pragma unroll
            for (int q = 0; q < 4; q++) d[mt][nt][q] = 0.f;

    const int nk = Dd / 32;    // 24
    load_stage(sb, A, Dd, Bw, Dd, tid);
    CP_COMMIT();

    for (int ks = 0; ks < nk; ks++) {
        uint32_t buf = (ks & 1) ? sb + STAGE : sb;
        if (ks + 1 < nk) {
            int kk = (ks + 1) * 32;
            uint32_t nbuf = ((ks + 1) & 1) ? sb + STAGE : sb;
            load_stage(nbuf, A + kk, Dd, Bw + kk, Dd, tid);
            CP_COMMIT();
            CP_WAIT1();
        } else {
            CP_WAIT0();
        }
        __syncthreads();
        compute_stage(buf, wm, wn, lane, d);
        __syncthreads();
    }

    // epilogue: + b1, gelu, * topv, store fp16
    const float* b1e = b1 + (size_t)e * FFf + f0;
    float w = g_topv[bk];
    int lrow = lane >> 2;
    int lcol = (lane & 3) * 2;
#pragma unroll
    for (int mt = 0; mt < 4; mt++) {
#pragma unroll
        for (int nt = 0; nt < 8; nt++) {
            int fc = wn * 64 + nt * 8 + lcol;
            float bb0 = b1e[fc];
            float bb1 = b1e[fc + 1];
#pragma unroll
            for (int half_i = 0; half_i < 2; half_i++) {
                int s = s0 + wm * 64 + mt * 16 + lrow + half_i * 8;
                float g0 = w * gelu_fast(d[mt][nt][2 * half_i]     + bb0);
                float g1 = w * gelu_fast(d[mt][nt][2 * half_i + 1] + bb1);
                __half2 hh = __halves2half2(__float2half_rn(g0), __float2half_rn(g1));
                size_t off = ((size_t)bk * Ss + s) * FFf + f0 + fc;
                *(uint32_t*)(g_hh + off) = *(uint32_t*)&hh;
            }
        }
    }
}

// ======================= GEMM2 (expert- and K-split, single fp16) =======================
// grid (Dd/128, Ss/128, B*K*2); z = bk*2 + slice (slice = half of FF)
__global__ __launch_bounds__(128, 2) void gemm2_mma(const float* __restrict__ b2) {
    extern __shared__ char smraw[];
    uint32_t sb = smem_u32(smraw);

    int tid = threadIdx.x, lane = tid & 31, warp = tid >> 5;
    int wm = warp & 1, wn = warp >> 1;
    int z     = blockIdx.z;
    int bk    = z >> 1;
    int slice = z & 1;
    int b  = bk >> 1;
    int e  = g_topi[bk];
    int s0 = blockIdx.y * 128, d0 = blockIdx.x * 128;
    int kbase = slice * (FFf / 2);

    const __half* A  = g_hh + ((size_t)bk * Ss + s0) * FFf + kbase;
    const __half* Bw = g_w2 + ((size_t)e * Dd + d0) * FFf + kbase;

    float d[4][8][4];
#pragma unroll
    for (int mt = 0; mt < 4; mt++)
#pragma unroll
        for (int nt = 0; nt < 8; nt++)
#pragma unroll
            for (int q = 0; q < 4; q++) d[mt][nt][q] = 0.f;

    const int nk = (FFf / 2) / 32;   // 48
    load_stage(sb, A, FFf, Bw, FFf, tid);
    CP_COMMIT();

    for (int ks = 0; ks < nk; ks++) {
        uint32_t buf = (ks & 1) ? sb + STAGE : sb;
        if (ks + 1 < nk) {
            int kk = (ks + 1) * 32;
            uint32_t nbuf = ((ks + 1) & 1) ? sb + STAGE : sb;
            load_stage(nbuf, A + kk, FFf, Bw + kk, FFf, tid);
            CP_COMMIT();
            CP_WAIT1();
        } else {
            CP_WAIT0();
        }
        __syncthreads();
        compute_stage(buf, wm, wn, lane, d);
        __syncthreads();
    }

    // epilogue: + topv * b2[e] (slice 0 only), write fp32 partial
    float tv = (slice == 0) ? g_topv[bk] : 0.f;
    const float* b2e = b2 + (size_t)e * Dd + d0;
    float* dst = g_mixp + (size_t)((bk & 1) * 2 + slice) * ((size_t)Bb * Ss * Dd);
    int lrow = lane >> 2;
    int lcol = (lane & 3) * 2;
#pragma unroll
    for (int mt = 0; mt < 4; mt++) {
#pragma unroll
        for (int nt = 0; nt < 8; nt++) {
            int nn = wn * 64 + nt * 8 + lcol;
            float bias0 = tv * b2e[nn];
            float bias1 = tv * b2e[nn + 1];
#pragma unroll
            for (int half_i = 0; half_i < 2; half_i++) {
                int s = s0 + wm * 64 + mt * 16 + lrow + half_i * 8;
                float2 o;
                o.x = d[mt][nt][2 * half_i]     + bias0;
                o.y = d[mt][nt][2 * half_i + 1] + bias1;
                *(float2*)(dst + ((size_t)b * Ss + s) * Dd + d0 + nn) = o;
            }
        }
    }
}

// ======================= kernel: out = x + LN(sum of 4 partials) =======================
__global__ void ln_kernel(const float* __restrict__ x,
                          const float* __restrict__ gamma,
                          const float* __restrict__ beta,
                          float* __restrict__ out) {
    int row = blockIdx.x;
    int tid = threadIdx.x;
    const size_t BSD = (size_t)Bb * Ss * Dd;
    const float* m0 = g_mixp + (size_t)row * Dd;
    const float* m1 = m0 + BSD;
    const float* m2 = m1 + BSD;
    const float* m3 = m2 + BSD;

    float v0 = m0[tid]       + m1[tid]       + m2[tid]       + m3[tid];
    float v1 = m0[tid + 256] + m1[tid + 256] + m2[tid + 256] + m3[tid + 256];
    float v2 = m0[tid + 512] + m1[tid + 512] + m2[tid + 512] + m3[tid + 512];
    __shared__ float red[256], red2[256];
    red[tid]  = v0 + v1 + v2;
    red2[tid] = v0 * v0 + v1 * v1 + v2 * v2;
    __syncthreads();
    for (int s = 128; s > 0; s >>= 1) {
        if (tid < s) { red[tid] += red[tid + s]; red2[tid] += red2[tid + s]; }
        __syncthreads();
    }
    __shared__ float smu, sinv;
    if (tid == 0) {
        float mu  = red[0] * (1.0f / Dd);
        float var = red2[0] * (1.0f / Dd) - mu * mu;
        smu = mu; sinv = rsqrtf(var + 1e-5f);
    }
    __syncthreads();
    float mu = smu, inv = sinv;
    const float* xr = x + (size_t)row * Dd;
    float* o = out + (size_t)row * Dd;
    float vv[3] = {v0, v1, v2};
#pragma unroll
    for (int q = 0; q < 3; q++) {
        int dd = tid + q * 256;
        o[dd] = xr[dd] + (vv[q] - mu) * inv * gamma[dd] + beta[dd];
    }
}

// ======================= launch =======================
extern "C" void kernel_launch(void* const* d_in, const int* in_sizes, int n_in,
                              void* d_out, int out_size) {
    const float* x   = (const float*)d_in[0];
    const float* ts  = (const float*)d_in[1];
    const float* W1  = (const float*)d_in[2];
    const float* b1  = (const float*)d_in[3];
    const float* W2  = (const float*)d_in[4];
    const float* b2  = (const float*)d_in[5];
    const float* rw  = (const float*)d_in[6];
    const float* rb  = (const float*)d_in[7];
    const float* gam = (const float*)d_in[8];
    const float* bet = (const float*)d_in[9];

    float* out   = (float*)d_out;
    float* probs = out + (size_t)Bb * Ss * Dd;

    cudaFuncSetAttribute(gemm1_mma, cudaFuncAttributeMaxDynamicSharedMemorySize, SMEM_BYTES);
    cudaFuncSetAttribute(gemm2_mma, cudaFuncAttributeMaxDynamicSharedMemorySize, SMEM_BYTES);

    router_kernel<<<Bb, 256>>>(x, ts, rw, rb, probs);
    split_x_kernel<<<(Bb * Ss * Dd) / 1024, 256>>>(x);
    split_w_kernel<<<dim3(FFf / 32, Dd / 32, Ee), dim3(32, 8)>>>(W1, 0, Dd, FFf);
    split_w_kernel<<<dim3(Dd / 32, FFf / 32, Ee), dim3(32, 8)>>>(W2, 1, FFf, Dd);

    gemm1_mma<<<dim3(FFf / 128, Ss / 128, Bb * KK), 128, SMEM_BYTES>>>(b1);
    gemm2_mma<<<dim3(Dd / 128, Ss / 128, Bb * KK * 2), 128, SMEM_BYTES>>>(b2);

    ln_kernel<<<Bb * Ss, 256>>>(x, gam, bet, out);
}